// round 14
// baseline (speedup 1.0000x reference)
#include <cuda_runtime.h>
#include <cuda_fp16.h>
#include <math.h>
#include <stdint.h>

typedef __half h16;

#define Bv 2
#define Sv 2048
#define DM 1024
#define NH 16
#define HD 64
#define DL 1024
#define TOK (Bv*Sv)          // 4096
#define LN_EPS 1e-5f
#define NORM_EPS 1e-12f

// ---- scratch (static device globals; allocation-free) ----
__device__ int8_t g_Aq8h[(size_t)TOK * DM], g_Aq8l[(size_t)TOK * DM];
__device__ float  g_sQr [(size_t)TOK];
__device__ int8_t g_Zq8h[(size_t)TOK * DL], g_Zq8l[(size_t)TOK * DL];
__device__ float  g_sZ  [(size_t)TOK];
__device__ int8_t g_W8h [(size_t)4096 * 1024], g_W8l[(size_t)4096 * 1024];
__device__ float  g_sW  [4096];
__device__ h16    g_WoT [(size_t)DM * DM];
__device__ float  g_Z   [(size_t)TOK * DL];
__device__ float  g_QRH [(size_t)TOK * 3 * DM];   // first 16MB also weight-T scratch
__device__ float  g_bqrh[3 * DM];
__device__ h16    g_Qc_h[(size_t)TOK * NH * 2 * HD], g_Qc_l[(size_t)TOK * NH * 2 * HD];
__device__ h16    g_Rc_h[(size_t)TOK * NH * 2 * HD];
__device__ h16    g_HvT_h[(size_t)Bv * NH * HD * Sv];
__device__ h16    g_Ao_h[(size_t)TOK * DM], g_Ao_l[(size_t)TOK * DM];

// ===========================================================================
// helpers
// ===========================================================================
__device__ __forceinline__ uint32_t smem_u32(const void* p) {
    uint32_t a;
    asm("{ .reg .u64 t; cvta.to.shared.u64 t, %1; cvt.u32.u64 %0, t; }"
        : "=r"(a) : "l"(p));
    return a;
}
__device__ __forceinline__ void mma_f16(float* d, const uint32_t* a, const uint32_t* b) {
    asm volatile(
        "mma.sync.aligned.m16n8k16.row.col.f32.f16.f16.f32 "
        "{%0,%1,%2,%3}, {%4,%5,%6,%7}, {%8,%9}, {%0,%1,%2,%3};"
        : "+f"(d[0]), "+f"(d[1]), "+f"(d[2]), "+f"(d[3])
        : "r"(a[0]), "r"(a[1]), "r"(a[2]), "r"(a[3]), "r"(b[0]), "r"(b[1]));
}
__device__ __forceinline__ void mma_s8(int* d, const uint32_t* a, const uint32_t* b) {
    asm volatile(
        "mma.sync.aligned.m16n8k32.row.col.s32.s8.s8.s32 "
        "{%0,%1,%2,%3}, {%4,%5,%6,%7}, {%8,%9}, {%0,%1,%2,%3};"
        : "+r"(d[0]), "+r"(d[1]), "+r"(d[2]), "+r"(d[3])
        : "r"(a[0]), "r"(a[1]), "r"(a[2]), "r"(a[3]), "r"(b[0]), "r"(b[1]));
}
__device__ __forceinline__ void ldmx4(uint32_t* r, uint32_t addr) {
    asm volatile("ldmatrix.sync.aligned.m8n8.x4.shared.b16 {%0,%1,%2,%3}, [%4];"
                 : "=r"(r[0]), "=r"(r[1]), "=r"(r[2]), "=r"(r[3]) : "r"(addr));
}
__device__ __forceinline__ void cpa16(uint32_t dst, const void* src) {
    asm volatile("cp.async.cg.shared.global [%0], [%1], 16;" :: "r"(dst), "l"(src));
}
__device__ __forceinline__ void cp_commit() { asm volatile("cp.async.commit_group;"); }
template<int N> __device__ __forceinline__ void cp_wait() {
    asm volatile("cp.async.wait_group %0;" :: "n"(N));
}
__device__ __forceinline__ uint32_t packh2(float a, float b) {
    __half2 t = __floats2half2_rn(a, b);
    return *reinterpret_cast<uint32_t*>(&t);
}
__device__ __forceinline__ void split4h(float4 v, uint2& hh, uint2& ll) {
    h16 ax = __float2half(v.x), ay = __float2half(v.y);
    h16 az = __float2half(v.z), aw = __float2half(v.w);
    __half2 h0 = {ax, ay}, h1 = {az, aw};
    hh.x = *reinterpret_cast<uint32_t*>(&h0); hh.y = *reinterpret_cast<uint32_t*>(&h1);
    ll.x = packh2(v.x - __half2float(ax), v.y - __half2float(ay));
    ll.y = packh2(v.z - __half2float(az), v.w - __half2float(aw));
}
__device__ __forceinline__ void split2h(float a, float b, uint32_t& hp, uint32_t& lp) {
    h16 ha = __float2half(a), hb = __float2half(b);
    __half2 t = {ha, hb};
    hp = *reinterpret_cast<uint32_t*>(&t);
    lp = packh2(a - __half2float(ha), b - __half2float(hb));
}

// ===========================================================================
// int8 2-digit NT GEMM: C = sA*sB*(16384*AhBh + 128*(AhBl+AlBh)) + bias
// BM=128, BN=128, BK=128 (bytes), 512 threads, double-buffer, ldmatrix
// ===========================================================================
__global__ void __launch_bounds__(512, 1)
gemm_s8(const int8_t* __restrict__ Ah_, const int8_t* __restrict__ Al_,
        const float* __restrict__ sA,
        const int8_t* __restrict__ Bh_, const int8_t* __restrict__ Bl_,
        const float* __restrict__ sB,
        const float* __restrict__ bias, float* __restrict__ Cf,
        int K, long lda, long ldb, long ldc)
{
    constexpr int BM = 128, BN = 128, BKB = 128, PAB = 144;     // byte pitch
    constexpr int OAh = 0, OAl = BM * PAB, OBh = 2 * BM * PAB, OBl = 2 * BM * PAB + BN * PAB;
    constexpr int SBUF = (2 * BM + 2 * BN) * PAB;               // 73728 B/stage
    constexpr int SP = BN + 4;

    extern __shared__ char smem_raw[];
    float* stg  = (float*)smem_raw;
    float* sa_s = (float*)(smem_raw + 68608);
    float* sb_s = (float*)(smem_raw + 69632);
    uint32_t smbase = smem_u32(smem_raw);

    int tid = threadIdx.x, wid = tid >> 5, lane = tid & 31;
    int gid = lane >> 2, tig = lane & 3;
    int seg = lane >> 3, sl = lane & 7;
    int wm0 = (wid >> 2) * 32, wn0 = (wid & 3) * 32;

    int row0 = blockIdx.y * BM, col0 = blockIdx.x * BN;
    const int8_t* AhP = Ah_ + (long)row0 * lda;
    const int8_t* AlP = Al_ + (long)row0 * lda;
    const int8_t* BhP = Bh_ + (long)col0 * ldb;
    const int8_t* BlP = Bl_ + (long)col0 * ldb;

    const int8_t* asrc[4]; uint32_t adst[4];
    const int8_t* bsrc[4]; uint32_t bdst[4];
#pragma unroll
    for (int i = 0; i < 4; i++) {
        int idx = tid + i * 512;
        int lo = idx >= 1024;
        int w = idx & 1023, r = w >> 3, kc = w & 7;
        asrc[i] = (lo ? AlP : AhP) + (long)r * lda + kc * 16;
        adst[i] = smbase + (uint32_t)((lo ? OAl : OAh) + r * PAB + kc * 16);
        bsrc[i] = (lo ? BlP : BhP) + (long)r * ldb + kc * 16;
        bdst[i] = smbase + (uint32_t)((lo ? OBl : OBh) + r * PAB + kc * 16);
    }

    uint32_t aadr_h[2], aadr_l[2], badr_h[2], badr_l[2];
#pragma unroll
    for (int mi = 0; mi < 2; mi++) {
        int rowA = wm0 + mi * 16 + (seg & 1) * 8 + sl;
        int colA = (seg >> 1) * 16;                 // bytes
        aadr_h[mi] = smbase + (uint32_t)(OAh + rowA * PAB + colA);
        aadr_l[mi] = smbase + (uint32_t)(OAl + rowA * PAB + colA);
    }
#pragma unroll
    for (int nj = 0; nj < 2; nj++) {
        int rowB = wn0 + nj * 16 + (seg >> 1) * 8 + sl;
        int colB = (seg & 1) * 16;
        badr_h[nj] = smbase + (uint32_t)(OBh + rowB * PAB + colB);
        badr_l[nj] = smbase + (uint32_t)(OBl + rowB * PAB + colB);
    }

    int hh[2][4][4], hl[2][4][4];
#pragma unroll
    for (int mi = 0; mi < 2; mi++)
#pragma unroll
        for (int ni = 0; ni < 4; ni++)
#pragma unroll
            for (int j = 0; j < 4; j++) { hh[mi][ni][j] = 0; hl[mi][ni][j] = 0; }

    const int NS = K / BKB;
    {
#pragma unroll
        for (int i = 0; i < 4; i++) cpa16(adst[i], asrc[i]);
#pragma unroll
        for (int i = 0; i < 4; i++) cpa16(bdst[i], bsrc[i]);
        cp_commit();
    }
    for (int s = 0; s < NS; s++) {
        if (s + 1 < NS) {
            long ko = (long)(s + 1) * BKB;
            uint32_t boff = ((s + 1) & 1) * (uint32_t)SBUF;
#pragma unroll
            for (int i = 0; i < 4; i++) cpa16(adst[i] + boff, asrc[i] + ko);
#pragma unroll
            for (int i = 0; i < 4; i++) cpa16(bdst[i] + boff, bsrc[i] + ko);
            cp_commit();
            cp_wait<1>();
        } else {
            cp_wait<0>();
        }
        __syncthreads();
        uint32_t soff = (s & 1) * (uint32_t)SBUF;
#pragma unroll
        for (int kk = 0; kk < 4; kk++) {            // k32 per step
            uint32_t off = soff + 32u * kk;
            uint32_t ah[2][4], al[2][4], bh[2][4], bl[2][4];
#pragma unroll
            for (int mi = 0; mi < 2; mi++) {
                ldmx4(ah[mi], aadr_h[mi] + off);
                ldmx4(al[mi], aadr_l[mi] + off);
            }
#pragma unroll
            for (int nj = 0; nj < 2; nj++) {
                ldmx4(bh[nj], badr_h[nj] + off);
                ldmx4(bl[nj], badr_l[nj] + off);
            }
#pragma unroll
            for (int mi = 0; mi < 2; mi++)
#pragma unroll
                for (int ni = 0; ni < 4; ni++) {
                    int nj = ni >> 1, sub = (ni & 1) * 2;
                    mma_s8(hh[mi][ni], ah[mi], &bh[nj][sub]);
                    mma_s8(hl[mi][ni], ah[mi], &bl[nj][sub]);
                    mma_s8(hl[mi][ni], al[mi], &bh[nj][sub]);
                }
        }
        __syncthreads();
    }

    if (tid < BM) { sa_s[tid] = sA[row0 + tid]; sb_s[tid] = sB[col0 + tid]; }
    __syncthreads();
#pragma unroll
    for (int mi = 0; mi < 2; mi++)
#pragma unroll
        for (int ni = 0; ni < 4; ni++) {
            int r = wm0 + mi * 16 + gid;
            int c = wn0 + ni * 8 + tig * 2;
            float s0 = sa_s[r], s1 = sa_s[r + 8];
            float t0 = sb_s[c], t1 = sb_s[c + 1];
            stg[r * SP + c]           = s0 * t0 * (16384.f * (float)hh[mi][ni][0] + 128.f * (float)hl[mi][ni][0]);
            stg[r * SP + c + 1]       = s0 * t1 * (16384.f * (float)hh[mi][ni][1] + 128.f * (float)hl[mi][ni][1]);
            stg[(r + 8) * SP + c]     = s1 * t0 * (16384.f * (float)hh[mi][ni][2] + 128.f * (float)hl[mi][ni][2]);
            stg[(r + 8) * SP + c + 1] = s1 * t1 * (16384.f * (float)hh[mi][ni][3] + 128.f * (float)hl[mi][ni][3]);
        }
    __syncthreads();
#pragma unroll
    for (int i = 0; i < 8; i++) {
        int idx = tid + i * 512;
        int row = idx >> 5, c4 = (idx & 31) * 4;
        float4 v = *(const float4*)(stg + row * SP + c4);
        int col = col0 + c4;
        float4 bv = *(const float4*)&bias[col];
        v.x += bv.x; v.y += bv.y; v.z += bv.z; v.w += bv.w;
        *(float4*)&Cf[(long)(row0 + row) * ldc + col] = v;
    }
}

// ===========================================================================
// fp16 2-term NT GEMM (Wo path) — unchanged from R8
// ===========================================================================
__global__ void __launch_bounds__(512, 1)
gemm_ps(const h16* __restrict__ Ah_, const h16* __restrict__ Al_,
        const h16* __restrict__ Bh_,
        const float* __restrict__ bias, float* __restrict__ Cf,
        int K, long lda, long ldb, long ldc)
{
    constexpr int BM = 128, BN = 128, BK = 64;
    constexpr int PA = 72;
    constexpr int SBUF = (2 * BM + BN) * PA;
    constexpr int OAh = 0, OAl = BM * PA, OBh = 2 * BM * PA;
    constexpr int AIT = 4, BIT = 2;
    constexpr int SP = BN + 4;

    extern __shared__ char smem_raw[];
    float* stg = (float*)smem_raw;
    uint32_t smbase = smem_u32(smem_raw);

    int tid = threadIdx.x, wid = tid >> 5, lane = tid & 31;
    int gid = lane >> 2, tig = lane & 3;
    int seg = lane >> 3, sl = lane & 7;
    int wm0 = (wid >> 2) * 32, wn0 = (wid & 3) * 32;

    int row0 = blockIdx.y * BM, col0 = blockIdx.x * BN;
    const h16* AhP = Ah_ + (long)row0 * lda;
    const h16* AlP = Al_ + (long)row0 * lda;
    const h16* BhP = Bh_ + (long)col0 * ldb;

    const h16* asrc[AIT]; uint32_t adst[AIT];
#pragma unroll
    for (int i = 0; i < AIT; i++) {
        int idx = tid + i * 512;
        int lo = idx >= BM * 8;
        int w = idx - lo * BM * 8;
        int r = w >> 3, kc = w & 7;
        asrc[i] = (lo ? AlP : AhP) + (long)r * lda + kc * 8;
        adst[i] = smbase + 2u * ((lo ? OAl : OAh) + r * PA + kc * 8);
    }
    const h16* bsrc[BIT]; uint32_t bdst[BIT];
#pragma unroll
    for (int i = 0; i < BIT; i++) {
        int idx = tid + i * 512;
        int r = idx >> 3, kc = idx & 7;
        bsrc[i] = BhP + (long)r * ldb + kc * 8;
        bdst[i] = smbase + 2u * (OBh + r * PA + kc * 8);
    }

    uint32_t aadr_h[2], aadr_l[2], badr[2];
#pragma unroll
    for (int mi = 0; mi < 2; mi++) {
        int rowA = wm0 + mi * 16 + (seg & 1) * 8 + sl;
        int colA = (seg >> 1) * 8;
        aadr_h[mi] = smbase + 2u * (OAh + rowA * PA + colA);
        aadr_l[mi] = smbase + 2u * (OAl + rowA * PA + colA);
    }
#pragma unroll
    for (int nj = 0; nj < 2; nj++) {
        int rowB = wn0 + nj * 16 + (seg >> 1) * 8 + sl;
        int colB = (seg & 1) * 8;
        badr[nj] = smbase + 2u * (OBh + rowB * PA + colB);
    }

    float acc[2][4][4];
#pragma unroll
    for (int mi = 0; mi < 2; mi++)
#pragma unroll
        for (int ni = 0; ni < 4; ni++)
#pragma unroll
            for (int j = 0; j < 4; j++) acc[mi][ni][j] = 0.f;

    const int NS = K / BK;
    {
#pragma unroll
        for (int i = 0; i < AIT; i++) cpa16(adst[i], asrc[i]);
#pragma unroll
        for (int i = 0; i < BIT; i++) cpa16(bdst[i], bsrc[i]);
        cp_commit();
    }
    for (int s = 0; s < NS; s++) {
        if (s + 1 < NS) {
            long ko = (long)(s + 1) * BK;
            uint32_t boff = ((s + 1) & 1) * (uint32_t)(SBUF * 2);
#pragma unroll
            for (int i = 0; i < AIT; i++) cpa16(adst[i] + boff, asrc[i] + ko);
#pragma unroll
            for (int i = 0; i < BIT; i++) cpa16(bdst[i] + boff, bsrc[i] + ko);
            cp_commit();
            cp_wait<1>();
        } else {
            cp_wait<0>();
        }
        __syncthreads();
        uint32_t soff = (s & 1) * (uint32_t)(SBUF * 2);
#pragma unroll
        for (int kk = 0; kk < 4; kk++) {
            uint32_t off = soff + 32u * kk;
            uint32_t ah[2][4], al[2][4], bh[2][4];
#pragma unroll
            for (int mi = 0; mi < 2; mi++) {
                ldmx4(ah[mi], aadr_h[mi] + off);
                ldmx4(al[mi], aadr_l[mi] + off);
            }
#pragma unroll
            for (int nj = 0; nj < 2; nj++) ldmx4(bh[nj], badr[nj] + off);
#pragma unroll
            for (int mi = 0; mi < 2; mi++)
#pragma unroll
                for (int ni = 0; ni < 4; ni++) {
                    int nj = ni >> 1, hf = (ni & 1) * 2;
                    mma_f16(acc[mi][ni], ah[mi], &bh[nj][hf]);
                    mma_f16(acc[mi][ni], al[mi], &bh[nj][hf]);
                }
        }
        __syncthreads();
    }

#pragma unroll
    for (int mi = 0; mi < 2; mi++)
#pragma unroll
        for (int ni = 0; ni < 4; ni++) {
            int r = wm0 + mi * 16 + gid;
            int c = wn0 + ni * 8 + tig * 2;
            stg[r * SP + c]           = acc[mi][ni][0];
            stg[r * SP + c + 1]       = acc[mi][ni][1];
            stg[(r + 8) * SP + c]     = acc[mi][ni][2];
            stg[(r + 8) * SP + c + 1] = acc[mi][ni][3];
        }
    __syncthreads();
#pragma unroll
    for (int i = 0; i < 8; i++) {
        int idx = tid + i * 512;
        int row = idx >> 5, c4 = (idx & 31) * 4;
        float4 v = *(const float4*)(stg + row * SP + c4);
        int col = col0 + c4;
        if (bias) {
            float4 bv = *(const float4*)&bias[col];
            v.x += bv.x; v.y += bv.y; v.z += bv.z; v.w += bv.w;
        }
        *(float4*)&Cf[(long)(row0 + row) * ldc + col] = v;
    }
}

// ===========================================================================
// Fused attention — unchanged from R8
// ===========================================================================
#define NT 32
#define QT 128
#define PQ 136
#define PH 72
#define STG_E (64*PQ + 64*PH)
#define ORH 0
#define OHH (64*PQ)
#define OQH (2*STG_E)
#define OQL (2*STG_E + QT*PQ)
#define FA_SMEM ((2*STG_E + 2*QT*PQ) * 2)

__global__ void __launch_bounds__(512, 1)
fused_attn_k(const h16* __restrict__ Qch, const h16* __restrict__ Qcl,
             const h16* __restrict__ Rch, const h16* __restrict__ Hth,
             h16* __restrict__ Aoh, h16* __restrict__ Aol)
{
    extern __shared__ char smem_raw[];
    uint32_t smbase = smem_u32(smem_raw);

    int tid = threadIdx.x, wid = tid >> 5, lane = tid & 31;
    int gid = lane >> 2, tig = lane & 3;
    int seg = lane >> 3, sl = lane & 7;
    int mw = wid >> 2, nw = wid & 3;

    int qt = blockIdx.x, z = blockIdx.z;
    int b = z >> 4, h = z & 15;
    int row0 = qt * QT;
    long qtok = ((long)(b * Sv + row0)) * 2048 + h * 128;
    long zHv = (long)z * HD * Sv;

#pragma unroll
    for (int i = 0; i < 8; i++) {
        int idx = tid + i * 512;
        int comp = idx >> 11;
        int w = idx & 2047;
        int r = w >> 4, kc = w & 15;
        const h16* src = (comp ? Qcl : Qch) + qtok + (long)r * 2048 + kc * 8;
        cpa16(smbase + 2u * ((comp ? OQL : OQH) + r * PQ + kc * 8), src);
    }
    {
        long rtok = ((long)(b * Sv)) * 2048 + h * 128;
#pragma unroll
        for (int i = 0; i < 2; i++) {
            int idx = tid + i * 512;
            int r = idx >> 4, kc = idx & 15;
            cpa16(smbase + 2u * (ORH + r * PQ + kc * 8), Rch + rtok + (long)r * 2048 + kc * 8);
        }
        {
            int n = tid >> 3, kc = tid & 7;
            cpa16(smbase + 2u * (OHH + n * PH + kc * 8), Hth + zHv + (long)n * 2048 + kc * 8);
        }
        cp_commit();
    }

    uint32_t qadr_h[2], qadr_l[2];
#pragma unroll
    for (int mi = 0; mi < 2; mi++) {
        int rowA = mw * 32 + mi * 16 + (seg & 1) * 8 + sl;
        int colA = (seg >> 1) * 8;
        qadr_h[mi] = smbase + 2u * (OQH + rowA * PQ + colA);
        qadr_l[mi] = smbase + 2u * (OQL + rowA * PQ + colA);
    }
    uint32_t radr;
    {
        int rowB = nw * 16 + (seg >> 1) * 8 + sl;
        int colB = (seg & 1) * 8;
        radr = smbase + 2u * (ORH + rowB * PQ + colB);
    }
    uint32_t hadr[4];
#pragma unroll
    for (int nj = 0; nj < 4; nj++) {
        int rowH = nj * 16 + (seg >> 1) * 8 + sl;
        int colH = (seg & 1) * 8 + nw * 16;
        hadr[nj] = smbase + 2u * (OHH + rowH * PH + colH);
    }

    float U[2][8][4];
#pragma unroll
    for (int mi = 0; mi < 2; mi++)
#pragma unroll
        for (int ni = 0; ni < 8; ni++)
#pragma unroll
            for (int j = 0; j < 4; j++) U[mi][ni][j] = 0.f;
    float sqacc[2][2] = {{0.f, 0.f}, {0.f, 0.f}};

    for (int t = 0; t < NT; t++) {
        if (t + 1 < NT) {
            uint32_t boff = ((t + 1) & 1) * (uint32_t)(STG_E * 2);
            long rtok = ((long)(b * Sv + (t + 1) * 64)) * 2048 + h * 128;
            long hoff = zHv + (t + 1) * 64;
#pragma unroll
            for (int i = 0; i < 2; i++) {
                int idx = tid + i * 512;
                int r = idx >> 4, kc = idx & 15;
                cpa16(smbase + boff + 2u * (ORH + r * PQ + kc * 8),
                      Rch + rtok + (long)r * 2048 + kc * 8);
            }
            {
                int n = tid >> 3, kc = tid & 7;
                cpa16(smbase + boff + 2u * (OHH + n * PH + kc * 8),
                      Hth + hoff + (long)n * 2048 + kc * 8);
            }
            cp_commit();
            cp_wait<1>();
        } else {
            cp_wait<0>();
        }
        __syncthreads();
        uint32_t soff = (t & 1) * (uint32_t)(STG_E * 2);

        float sacc[2][2][4];
#pragma unroll
        for (int mi = 0; mi < 2; mi++)
#pragma unroll
            for (int ni = 0; ni < 2; ni++)
#pragma unroll
                for (int j = 0; j < 4; j++) sacc[mi][ni][j] = 0.f;
#pragma unroll
        for (int kk = 0; kk < 8; kk++) {
            uint32_t koff = 32u * kk;
            uint32_t ah[2][4], al[2][4], bh[4];
#pragma unroll
            for (int mi = 0; mi < 2; mi++) {
                ldmx4(ah[mi], qadr_h[mi] + koff);
                ldmx4(al[mi], qadr_l[mi] + koff);
            }
            ldmx4(bh, radr + soff + koff);
#pragma unroll
            for (int mi = 0; mi < 2; mi++)
#pragma unroll
                for (int ni = 0; ni < 2; ni++) {
                    mma_f16(sacc[mi][ni], ah[mi], &bh[ni * 2]);
                    mma_f16(sacc[mi][ni], al[mi], &bh[ni * 2]);
                }
        }
#pragma unroll
        for (int mi = 0; mi < 2; mi++) {
            float s0 = 0.f, s1 = 0.f;
#pragma unroll
            for (int ni = 0; ni < 2; ni++) {
                s0 += sacc[mi][ni][0] * sacc[mi][ni][0] + sacc[mi][ni][1] * sacc[mi][ni][1];
                s1 += sacc[mi][ni][2] * sacc[mi][ni][2] + sacc[mi][ni][3] * sacc[mi][ni][3];
            }
            sqacc[mi][0] += s0; sqacc[mi][1] += s1;
        }
        uint32_t a2h[2][4], a2l[2][4];
#pragma unroll
        for (int mi = 0; mi < 2; mi++) {
            split2h(sacc[mi][0][0], sacc[mi][0][1], a2h[mi][0], a2l[mi][0]);
            split2h(sacc[mi][0][2], sacc[mi][0][3], a2h[mi][1], a2l[mi][1]);
            split2h(sacc[mi][1][0], sacc[mi][1][1], a2h[mi][2], a2l[mi][2]);
            split2h(sacc[mi][1][2], sacc[mi][1][3], a2h[mi][3], a2l[mi][3]);
        }
#pragma unroll
        for (int nj = 0; nj < 4; nj++) {
            uint32_t bh2[4];
            ldmx4(bh2, hadr[nj] + soff);
#pragma unroll
            for (int hf = 0; hf < 2; hf++) {
                int ni = nj * 2 + hf;
#pragma unroll
                for (int mi = 0; mi < 2; mi++) {
                    mma_f16(U[mi][ni], a2h[mi], &bh2[hf * 2]);
                    mma_f16(U[mi][ni], a2l[mi], &bh2[hf * 2]);
                }
            }
        }
        __syncthreads();
    }

    float* Ured = (float*)smem_raw;
    float* sq = (float*)(smem_raw + QT * 68 * 4);
    if (tid < QT) sq[tid] = 0.f;
    __syncthreads();
#pragma unroll
    for (int mi = 0; mi < 2; mi++)
#pragma unroll
        for (int hh = 0; hh < 2; hh++) {
            float v = sqacc[mi][hh];
            v += __shfl_xor_sync(0xFFFFFFFF, v, 1);
            v += __shfl_xor_sync(0xFFFFFFFF, v, 2);
            if (tig == 0) atomicAdd(&sq[mw * 32 + mi * 16 + gid + hh * 8], v);
        }
    __syncthreads();
    if (tid < QT) sq[tid] = 1.0f / fmaxf(sqrtf(sq[tid]), NORM_EPS);
    for (int w = 0; w < 4; w++) {
        if (nw == w) {
#pragma unroll
            for (int mi = 0; mi < 2; mi++)
#pragma unroll
                for (int ni = 0; ni < 8; ni++) {
                    int r = mw * 32 + mi * 16 + gid;
                    int c = ni * 8 + tig * 2;
                    if (w == 0) {
                        Ured[r * 68 + c]           = U[mi][ni][0];
                        Ured[r * 68 + c + 1]       = U[mi][ni][1];
                        Ured[(r + 8) * 68 + c]     = U[mi][ni][2];
                        Ured[(r + 8) * 68 + c + 1] = U[mi][ni][3];
                    } else {
                        Ured[r * 68 + c]           += U[mi][ni][0];
                        Ured[r * 68 + c + 1]       += U[mi][ni][1];
                        Ured[(r + 8) * 68 + c]     += U[mi][ni][2];
                        Ured[(r + 8) * 68 + c + 1] += U[mi][ni][3];
                    }
                }
        }
        __syncthreads();
    }
#pragma unroll
    for (int i = 0; i < 4; i++) {
        int idx = tid + i * 512;
        int r = idx >> 4, c4 = (idx & 15) * 4;
        float sc = sq[r];
        float4 v = *(const float4*)(Ured + r * 68 + c4);
        v.x *= sc; v.y *= sc; v.z *= sc; v.w *= sc;
        uint2 hh, ll;
        split4h(v, hh, ll);
        long gpos = ((long)(b * Sv + row0 + r)) * DM + h * 64 + c4;
        *(uint2*)&Aoh[gpos] = hh;
        *(uint2*)&Aol[gpos] = ll;
    }
}

// ===========================================================================
// small kernels
// ===========================================================================
// per-row int8 2-digit quantization (row length 1024)
__global__ void quant_rows_k(const float* __restrict__ X, long ldx,
                             int8_t* __restrict__ Xh, int8_t* __restrict__ Xl,
                             float* __restrict__ sc)
{
    __shared__ float red[256];
    int tid = threadIdx.x;
    const float* row = X + (long)blockIdx.x * ldx;
    float v[4]; float m = 0.f;
#pragma unroll
    for (int t = 0; t < 4; t++) { v[t] = row[tid + t * 256]; m = fmaxf(m, fabsf(v[t])); }
    red[tid] = m; __syncthreads();
    for (int off = 128; off > 0; off >>= 1) {
        if (tid < off) red[tid] = fmaxf(red[tid], red[tid + off]);
        __syncthreads();
    }
    float s = fmaxf(red[0], 1e-20f) * (1.0f / 16256.0f);
    float inv = 1.0f / s;
    long base = (long)blockIdx.x * 1024;
#pragma unroll
    for (int t = 0; t < 4; t++) {
        int i = tid + t * 256;
        float u = v[t] * inv;
        float hq = rintf(u * (1.0f / 128.0f));
        hq = fminf(fmaxf(hq, -127.f), 127.f);
        float lq = rintf(u - 128.f * hq);
        lq = fminf(fmaxf(lq, -127.f), 127.f);
        Xh[base + i] = (int8_t)hq;
        Xl[base + i] = (int8_t)lq;
    }
    if (tid == 0) sc[blockIdx.x] = s;
}

// LayerNorm + int8 2-digit quantize
__global__ void ln_quant_k(const float* __restrict__ Z,
                           int8_t* __restrict__ oh, int8_t* __restrict__ ol,
                           float* __restrict__ sc,
                           const float* __restrict__ g, const float* __restrict__ be)
{
    __shared__ float red[256];
    int tid = threadIdx.x;
    const float* row = Z + (long)blockIdx.x * DL;
    float v[4];
#pragma unroll
    for (int t = 0; t < 4; t++) v[t] = row[tid + t * 256];
    float s = v[0] + v[1] + v[2] + v[3];
    red[tid] = s; __syncthreads();
    for (int off = 128; off > 0; off >>= 1) {
        if (tid < off) red[tid] += red[tid + off];
        __syncthreads();
    }
    float mu = red[0] * (1.0f / DL);
    __syncthreads();
    float vs = 0.f;
#pragma unroll
    for (int t = 0; t < 4; t++) { float d = v[t] - mu; vs += d * d; }
    red[tid] = vs; __syncthreads();
    for (int off = 128; off > 0; off >>= 1) {
        if (tid < off) red[tid] += red[tid + off];
        __syncthreads();
    }
    float rstd = rsqrtf(red[0] * (1.0f / DL) + LN_EPS);
    __syncthreads();
    float o[4]; float m = 0.f;
#pragma unroll
    for (int t = 0; t < 4; t++) {
        int i = tid + t * 256;
        o[t] = (v[t] - mu) * rstd * g[i] + be[i];
        m = fmaxf(m, fabsf(o[t]));
    }
    red[tid] = m; __syncthreads();
    for (int off = 128; off > 0; off >>= 1) {
        if (tid < off) red[tid] = fmaxf(red[tid], red[tid + off]);
        __syncthreads();
    }
    float sq = fmaxf(red[0], 1e-20f) * (1.0f / 16256.0f);
    float inv = 1.0f / sq;
    long base = (long)blockIdx.x * DL;
#pragma unroll
    for (int t = 0; t < 4; t++) {
        int i = tid + t * 256;
        float u = o[t] * inv;
        float hq = rintf(u * (1.0f / 128.0f));
        hq = fminf(fmaxf(hq, -127.f), 127.f);
        float lq = rintf(u - 128.f * hq);
        lq = fminf(fmaxf(lq, -127.f), 127.f);
        oh[base + i] = (int8_t)hq;
        ol[base + i] = (int8_t)lq;
    }
    if (tid == 0) sc[blockIdx.x] = sq;
}

// fp32 tiled transpose
__global__ void transpose_f32_k(const float* __restrict__ in, float* __restrict__ out,
                                long ldi, long ldo)
{
    __shared__ float t[32][33];
    int x0 = blockIdx.x * 32, y0 = blockIdx.y * 32;
    int tx = threadIdx.x & 31, ty = threadIdx.x >> 5;
#pragma unroll
    for (int i = 0; i < 4; i++)
        t[ty + i * 8][tx] = in[(long)(y0 + ty + i * 8) * ldi + x0 + tx];
    __syncthreads();
#pragma unroll
    for (int i = 0; i < 4; i++)
        out[(long)(x0 + ty + i * 8) * ldo + y0 + tx] = t[tx][ty + i * 8];
}

// transpose + round-to-fp16
__global__ void transpose_round_k(const float* __restrict__ in,
                                  h16* __restrict__ oh,
                                  long ldi, long ldo, int H,
                                  long sIb, long sIh, long sOz)
{
    __shared__ float t[32][33];
    int z = blockIdx.z, b = z / H, h = z - b * H;
    in += (long)b * sIb + (long)h * sIh;
    oh += (long)z * sOz;
    int x0 = blockIdx.x * 32, y0 = blockIdx.y * 32;
    int tx = threadIdx.x & 31, ty = threadIdx.x >> 5;
#pragma unroll
    for (int i = 0; i < 4; i++)
        t[ty + i * 8][tx] = in[(long)(y0 + ty + i * 8) * ldi + x0 + tx];
    __syncthreads();
#pragma unroll
    for (int i = 0; i < 4; i++)
        oh[(long)(x0 + ty + i * 8) * ldo + y0 + tx] = __float2half(t[tx][ty + i * 8]);
}

// phasor for Q and R in one launch (blockIdx.y: 0 = Q split, 1 = R hi-only)
__global__ void phasor2_k(const float* __restrict__ QRH,
                          h16* __restrict__ Qch, h16* __restrict__ Qcl,
                          h16* __restrict__ Rch,
                          const float* __restrict__ Wphi, const float* __restrict__ bphi)
{
    __shared__ float W[HD][HD];
    __shared__ float qrow[4][HD + 4];
    int tid = threadIdx.x;
    int j = tid & 63, g = tid >> 6;
    int which = blockIdx.y;
    for (int i = tid; i < HD * HD; i += 256) W[i >> 6][i & 63] = Wphi[i];
    __syncthreads();
    const float* base = QRH + (long)blockIdx.x * (3 * DM) + (which ? DM : 0);
    h16* oh = which ? Rch : Qch;
    h16* ol = which ? (h16*)nullptr : Qcl;
    long obase = (long)blockIdx.x * (NH * 2 * HD);
    float bj = bphi[j];
    for (int hb = 0; hb < NH; hb += 4) {
        int h = hb + g;
        qrow[g][j] = base[h * HD + j];
        __syncthreads();
        float phi = bj;
#pragma unroll 16
        for (int d = 0; d < HD; d++) phi += qrow[g][d] * W[d][j];
        float q = qrow[g][j];
        float sp, cp;
        sincosf(phi, &sp, &cp);
        float vc = q * cp, vsn = q * sp;
        h16 hc = __float2half(vc), hs = __float2half(vsn);
        long oc = obase + h * 2 * HD + j;
        oh[oc] = hc;
        oh[oc + HD] = hs;
        if (ol) {
            ol[oc] = __float2half(vc - __half2float(hc));
            ol[oc + HD] = __float2half(vsn - __half2float(hs));
        }
        __syncthreads();
    }
}

__global__ void concat3_k(const float* __restrict__ a, const float* __restrict__ b,
                          const float* __restrict__ c, float* __restrict__ o)
{
    int i = blockIdx.x * 256 + threadIdx.x;
    if (i < DM) o[i] = a[i];
    else if (i < 2 * DM) o[i] = b[i - DM];
    else if (i < 3 * DM) o[i] = c[i - 2 * DM];
}

// ===========================================================================
extern "C" void kernel_launch(void* const* d_in, const int* in_sizes, int n_in,
                              void* d_out, int out_size)
{
    const float* query = (const float*)d_in[0];
    const float* Wz   = (const float*)d_in[3];
    const float* bz   = (const float*)d_in[4];
    const float* ln_g = (const float*)d_in[5];
    const float* ln_b = (const float*)d_in[6];
    const float* Wq   = (const float*)d_in[7];
    const float* bq   = (const float*)d_in[8];
    const float* Wr   = (const float*)d_in[9];
    const float* br   = (const float*)d_in[10];
    const float* Wh   = (const float*)d_in[11];
    const float* bh   = (const float*)d_in[12];
    const float* Wphi = (const float*)d_in[13];
    const float* bphi = (const float*)d_in[14];
    const float* Wo   = (const float*)d_in[15];
    const float* bo   = (const float*)d_in[16];
    float* out = (float*)d_out;

    int8_t *Aq8h, *Aq8l, *Zq8h, *Zq8l, *W8h, *W8l;
    float *sQr, *sZ, *sW, *Z, *QRH, *bqrh;
    h16 *WoT, *Qc_h, *Qc_l, *Rc_h, *HvT_h, *Ao_h, *Ao_l;
    cudaGetSymbolAddress((void**)&Aq8h, g_Aq8h); cudaGetSymbolAddress((void**)&Aq8l, g_Aq8l);
    cudaGetSymbolAddress((void**)&sQr,  g_sQr);
    cudaGetSymbolAddress((void**)&Zq8h, g_Zq8h); cudaGetSymbolAddress((void**)&Zq8l, g_Zq8l);
    cudaGetSymbolAddress((void**)&sZ,   g_sZ);
    cudaGetSymbolAddress((void**)&W8h,  g_W8h);  cudaGetSymbolAddress((void**)&W8l,  g_W8l);
    cudaGetSymbolAddress((void**)&sW,   g_sW);
    cudaGetSymbolAddress((void**)&WoT,  g_WoT);
    cudaGetSymbolAddress((void**)&Z,    g_Z);
    cudaGetSymbolAddress((void**)&QRH,  g_QRH);
    cudaGetSymbolAddress((void**)&bqrh, g_bqrh);
    cudaGetSymbolAddress((void**)&Qc_h, g_Qc_h); cudaGetSymbolAddress((void**)&Qc_l, g_Qc_l);
    cudaGetSymbolAddress((void**)&Rc_h, g_Rc_h);
    cudaGetSymbolAddress((void**)&HvT_h, g_HvT_h);
    cudaGetSymbolAddress((void**)&Ao_h, g_Ao_h); cudaGetSymbolAddress((void**)&Ao_l, g_Ao_l);

    const int SM8 = (2 * 128 + 2 * 128) * 144 * 2;     // 147,456 B
    const int SMG = (2 * 128 + 128) * 72 * 2 * 2;      // 110,592 B
    cudaFuncSetAttribute(gemm_s8, cudaFuncAttributeMaxDynamicSharedMemorySize, SM8);
    cudaFuncSetAttribute(gemm_ps, cudaFuncAttributeMaxDynamicSharedMemorySize, SMG);
    cudaFuncSetAttribute(fused_attn_k, cudaFuncAttributeMaxDynamicSharedMemorySize, FA_SMEM);

    dim3 blk(256), gblk(512);
    float* scr = QRH;   // 16 MB weight-transpose scratch inside QRH buffer

    // 0) weight prep: fp32 transposes -> scr rows [WzT|WqT|WrT|WhT], quantize rows
    transpose_f32_k<<<dim3(32, 32, 1), blk>>>(Wz, scr,                          DL, DM);
    transpose_f32_k<<<dim3(32, 32, 1), blk>>>(Wq, scr + (size_t)1024 * 1024,     DM, DL);
    transpose_f32_k<<<dim3(32, 32, 1), blk>>>(Wr, scr + (size_t)2 * 1024 * 1024, DM, DL);
    transpose_f32_k<<<dim3(32, 32, 1), blk>>>(Wh, scr + (size_t)3 * 1024 * 1024, DM, DL);
    quant_rows_k<<<4096, blk>>>(scr, 1024, W8h, W8l, sW);
    transpose_round_k<<<dim3(32, 32, 1), blk>>>(Wo, WoT, DM, DM, 1, 0, 0, 0);
    quant_rows_k<<<TOK, blk>>>(query, DM, Aq8h, Aq8l, sQr);
    concat3_k<<<12, blk>>>(bq, br, bh, bqrh);

    // 1) Z = query @ Wz + bz   (int8 2-digit)
    gemm_s8<<<dim3(DL / 128, TOK / 128, 1), gblk, SM8>>>(
        Aq8h, Aq8l, sQr, W8h, W8l, sW, bz, Z, DM, DM, DM, DL);

    // 2) LayerNorm -> int8 quant
    ln_quant_k<<<TOK, blk>>>(Z, Zq8h, Zq8l, sZ, ln_g, ln_b);

    // 3) fused Q|R|H projection (N=3072, int8 2-digit)
    gemm_s8<<<dim3(3 * DM / 128, TOK / 128, 1), gblk, SM8>>>(
        Zq8h, Zq8l, sZ,
        W8h + (size_t)1024 * 1024, W8l + (size_t)1024 * 1024, sW + 1024,
        bqrh, QRH, DL, DL, DL, 3 * DM);

    // 4) phasor -> Qc split / Rc hi (one launch)
    phasor2_k<<<dim3(TOK, 2, 1), blk>>>(QRH, Qc_h, Qc_l, Rc_h, Wphi, bphi);

    // 5) Hv^T per (b,h), fp16 (Hv = QRH cols [2048,3072))
    transpose_round_k<<<dim3(HD / 32, Sv / 32, Bv * NH), blk>>>(
        QRH + 2 * DM, HvT_h, 3 * DM, Sv, NH, (long)Sv * 3 * DM, HD, (long)HD * Sv);

    // 6) fused attention -> Ao split
    fused_attn_k<<<dim3(Sv / QT, 1, Bv * NH), gblk, FA_SMEM>>>(
        Qc_h, Qc_l, Rc_h, HvT_h, Ao_h, Ao_l);

    // 7) out = Ao @ Wo + bo   (fp16 2-term)
    gemm_ps<<<dim3(DM / 128, TOK / 128, 1), gblk, SMG>>>(
        Ao_h, Ao_l, WoT, bo, out, DM, DM, DM, DM);
}

// round 15
// speedup vs baseline: 1.9769x; 1.9769x over previous
#include <cuda_runtime.h>
#include <cuda_fp16.h>
#include <math.h>
#include <stdint.h>

typedef __half h16;

#define Bv 2
#define Sv 2048
#define DM 1024
#define NH 16
#define HD 64
#define DL 1024
#define TOK (Bv*Sv)          // 4096
#define LN_EPS 1e-5f
#define NORM_EPS 1e-12f

// ---- scratch (static device globals; allocation-free) ----
__device__ h16   g_Qs_h[(size_t)TOK * DM],  g_Qs_l[(size_t)TOK * DM];
__device__ h16   g_WT_h[5 * (size_t)DM * DL];                 // weights: hi only
__device__ float g_Z   [(size_t)TOK * DL];
__device__ h16   g_Zs_h[(size_t)TOK * DL],  g_Zs_l[(size_t)TOK * DL];
__device__ float g_QRH [(size_t)TOK * 3 * DM];
__device__ float g_bqrh[3 * DM];
__device__ h16   g_Qc_h[(size_t)TOK * NH * 2 * HD], g_Qc_l[(size_t)TOK * NH * 2 * HD];
__device__ h16   g_Rc_h[(size_t)TOK * NH * 2 * HD];           // hi only (B side)
__device__ h16   g_HvT_h[(size_t)Bv * NH * HD * Sv];          // hi only (B side)
__device__ h16   g_Ao_h[(size_t)TOK * DM], g_Ao_l[(size_t)TOK * DM];

// ===========================================================================
// helpers
// ===========================================================================
__device__ __forceinline__ uint32_t smem_u32(const void* p) {
    uint32_t a;
    asm("{ .reg .u64 t; cvta.to.shared.u64 t, %1; cvt.u32.u64 %0, t; }"
        : "=r"(a) : "l"(p));
    return a;
}
__device__ __forceinline__ void mma_f16(float* d, const uint32_t* a, const uint32_t* b) {
    asm volatile(
        "mma.sync.aligned.m16n8k16.row.col.f32.f16.f16.f32 "
        "{%0,%1,%2,%3}, {%4,%5,%6,%7}, {%8,%9}, {%0,%1,%2,%3};"
        : "+f"(d[0]), "+f"(d[1]), "+f"(d[2]), "+f"(d[3])
        : "r"(a[0]), "r"(a[1]), "r"(a[2]), "r"(a[3]), "r"(b[0]), "r"(b[1]));
}
__device__ __forceinline__ void ldmx4(uint32_t* r, uint32_t addr) {
    asm volatile("ldmatrix.sync.aligned.m8n8.x4.shared.b16 {%0,%1,%2,%3}, [%4];"
                 : "=r"(r[0]), "=r"(r[1]), "=r"(r[2]), "=r"(r[3]) : "r"(addr));
}
__device__ __forceinline__ void cpa16(uint32_t dst, const void* src) {
    asm volatile("cp.async.cg.shared.global [%0], [%1], 16;" :: "r"(dst), "l"(src));
}
__device__ __forceinline__ void cp_commit() { asm volatile("cp.async.commit_group;"); }
template<int N> __device__ __forceinline__ void cp_wait() {
    asm volatile("cp.async.wait_group %0;" :: "n"(N));
}
__device__ __forceinline__ uint32_t packh2(float a, float b) {
    __half2 t = __floats2half2_rn(a, b);
    return *reinterpret_cast<uint32_t*>(&t);
}
__device__ __forceinline__ void split4h(float4 v, uint2& hh, uint2& ll) {
    h16 ax = __float2half(v.x), ay = __float2half(v.y);
    h16 az = __float2half(v.z), aw = __float2half(v.w);
    __half2 h0 = {ax, ay}, h1 = {az, aw};
    hh.x = *reinterpret_cast<uint32_t*>(&h0); hh.y = *reinterpret_cast<uint32_t*>(&h1);
    ll.x = packh2(v.x - __half2float(ax), v.y - __half2float(ay));
    ll.y = packh2(v.z - __half2float(az), v.w - __half2float(aw));
}

// ===========================================================================
// NT GEMM: C = (Ah+Al) @ Bh^T (+bias). A fp16 split, B fp16 rounded. 2 MMAs.
// BM=128, BN=128, BK=64, 512 threads, double-buffered cp.async, ldmatrix
// ===========================================================================
__global__ void __launch_bounds__(512, 1)
gemm_ps(const h16* __restrict__ Ah_, const h16* __restrict__ Al_,
        const h16* __restrict__ Bh_,
        const float* __restrict__ bias, float* __restrict__ Cf,
        int K, long lda, long ldb, long ldc)
{
    constexpr int BM = 128, BN = 128, BK = 64;
    constexpr int PA = 72;
    constexpr int SBUF = (2 * BM + BN) * PA;          // 27648 elems
    constexpr int OAh = 0, OAl = BM * PA, OBh = 2 * BM * PA;
    constexpr int AIT = 4, BIT = 2;
    constexpr int SP = BN + 4;

    extern __shared__ char smem_raw[];
    float* stg = (float*)smem_raw;
    uint32_t smbase = smem_u32(smem_raw);

    int tid = threadIdx.x, wid = tid >> 5, lane = tid & 31;
    int gid = lane >> 2, tig = lane & 3;
    int seg = lane >> 3, sl = lane & 7;
    int wm0 = (wid >> 2) * 32, wn0 = (wid & 3) * 32;

    int row0 = blockIdx.y * BM, col0 = blockIdx.x * BN;
    const h16* AhP = Ah_ + (long)row0 * lda;
    const h16* AlP = Al_ + (long)row0 * lda;
    const h16* BhP = Bh_ + (long)col0 * ldb;

    const h16* asrc[AIT]; uint32_t adst[AIT];
#pragma unroll
    for (int i = 0; i < AIT; i++) {
        int idx = tid + i * 512;
        int lo = idx >= BM * 8;
        int w = idx - lo * BM * 8;
        int r = w >> 3, kc = w & 7;
        asrc[i] = (lo ? AlP : AhP) + (long)r * lda + kc * 8;
        adst[i] = smbase + 2u * ((lo ? OAl : OAh) + r * PA + kc * 8);
    }
    const h16* bsrc[BIT]; uint32_t bdst[BIT];
#pragma unroll
    for (int i = 0; i < BIT; i++) {
        int idx = tid + i * 512;
        int r = idx >> 3, kc = idx & 7;
        bsrc[i] = BhP + (long)r * ldb + kc * 8;
        bdst[i] = smbase + 2u * (OBh + r * PA + kc * 8);
    }

    uint32_t aadr_h[2], aadr_l[2], badr[2];
#pragma unroll
    for (int mi = 0; mi < 2; mi++) {
        int rowA = wm0 + mi * 16 + (seg & 1) * 8 + sl;
        int colA = (seg >> 1) * 8;
        aadr_h[mi] = smbase + 2u * (OAh + rowA * PA + colA);
        aadr_l[mi] = smbase + 2u * (OAl + rowA * PA + colA);
    }
#pragma unroll
    for (int nj = 0; nj < 2; nj++) {
        int rowB = wn0 + nj * 16 + (seg >> 1) * 8 + sl;
        int colB = (seg & 1) * 8;
        badr[nj] = smbase + 2u * (OBh + rowB * PA + colB);
    }

    float acc[2][4][4];
#pragma unroll
    for (int mi = 0; mi < 2; mi++)
#pragma unroll
        for (int ni = 0; ni < 4; ni++)
#pragma unroll
            for (int j = 0; j < 4; j++) acc[mi][ni][j] = 0.f;

    const int NS = K / BK;
    {
#pragma unroll
        for (int i = 0; i < AIT; i++) cpa16(adst[i], asrc[i]);
#pragma unroll
        for (int i = 0; i < BIT; i++) cpa16(bdst[i], bsrc[i]);
        cp_commit();
    }
    for (int s = 0; s < NS; s++) {
        if (s + 1 < NS) {
            long ko = (long)(s + 1) * BK;
            uint32_t boff = ((s + 1) & 1) * (uint32_t)(SBUF * 2);
#pragma unroll
            for (int i = 0; i < AIT; i++) cpa16(adst[i] + boff, asrc[i] + ko);
#pragma unroll
            for (int i = 0; i < BIT; i++) cpa16(bdst[i] + boff, bsrc[i] + ko);
            cp_commit();
            cp_wait<1>();
        } else {
            cp_wait<0>();
        }
        __syncthreads();
        uint32_t soff = (s & 1) * (uint32_t)(SBUF * 2);
#pragma unroll
        for (int kk = 0; kk < 4; kk++) {
            uint32_t off = soff + 32u * kk;
            uint32_t ah[2][4], al[2][4], bh[2][4];
#pragma unroll
            for (int mi = 0; mi < 2; mi++) {
                ldmx4(ah[mi], aadr_h[mi] + off);
                ldmx4(al[mi], aadr_l[mi] + off);
            }
#pragma unroll
            for (int nj = 0; nj < 2; nj++) ldmx4(bh[nj], badr[nj] + off);
#pragma unroll
            for (int mi = 0; mi < 2; mi++)
#pragma unroll
                for (int ni = 0; ni < 4; ni++) {
                    int nj = ni >> 1, hf = (ni & 1) * 2;
                    mma_f16(acc[mi][ni], ah[mi], &bh[nj][hf]);
                    mma_f16(acc[mi][ni], al[mi], &bh[nj][hf]);
                }
        }
        __syncthreads();
    }

#pragma unroll
    for (int mi = 0; mi < 2; mi++)
#pragma unroll
        for (int ni = 0; ni < 4; ni++) {
            int r = wm0 + mi * 16 + gid;
            int c = wn0 + ni * 8 + tig * 2;
            stg[r * SP + c]           = acc[mi][ni][0];
            stg[r * SP + c + 1]       = acc[mi][ni][1];
            stg[(r + 8) * SP + c]     = acc[mi][ni][2];
            stg[(r + 8) * SP + c + 1] = acc[mi][ni][3];
        }
    __syncthreads();
#pragma unroll
    for (int i = 0; i < 8; i++) {
        int idx = tid + i * 512;
        int row = idx >> 5, c4 = (idx & 31) * 4;
        float4 v = *(const float4*)(stg + row * SP + c4);
        int col = col0 + c4;
        if (bias) {
            float4 bv = *(const float4*)&bias[col];
            v.x += bv.x; v.y += bv.y; v.z += bv.z; v.w += bv.w;
        }
        *(float4*)&Cf[(long)(row0 + row) * ldc + col] = v;
    }
}

// ===========================================================================
// Fused attention: per (b,h,q-tile 128): S = Qc@Rc^T (regs), sumsq, U += S@Hv,
// then U / max(||row||,eps) -> Ao split. 512 threads, 16 warps (4m x 4n).
// Phase A: Qc split (2 MMAs). Phase B: S *rounded* to fp16 (1 MMA).
// ===========================================================================
#define NT 32            // r-tiles of 64
#define QT 128
#define PQ 136
#define PH 72
#define STG_E (64*PQ + 64*PH)        // 13312 elems per stage
#define ORH 0
#define OHH (64*PQ)
#define OQH (2*STG_E)
#define OQL (2*STG_E + QT*PQ)
#define FA_SMEM ((2*STG_E + 2*QT*PQ) * 2)   // 122,880 bytes

__global__ void __launch_bounds__(512, 1)
fused_attn_k(const h16* __restrict__ Qch, const h16* __restrict__ Qcl,
             const h16* __restrict__ Rch, const h16* __restrict__ Hth,
             h16* __restrict__ Aoh, h16* __restrict__ Aol)
{
    extern __shared__ char smem_raw[];
    uint32_t smbase = smem_u32(smem_raw);

    int tid = threadIdx.x, wid = tid >> 5, lane = tid & 31;
    int gid = lane >> 2, tig = lane & 3;
    int seg = lane >> 3, sl = lane & 7;
    int mw = wid >> 2, nw = wid & 3;

    int qt = blockIdx.x, z = blockIdx.z;
    int b = z >> 4, h = z & 15;
    int row0 = qt * QT;
    long qtok = ((long)(b * Sv + row0)) * 2048 + h * 128;
    long zHv = (long)z * HD * Sv;

    // ---- Qc prologue (hi+lo, 128 rows x 128 cols) ----
#pragma unroll
    for (int i = 0; i < 8; i++) {
        int idx = tid + i * 512;
        int comp = idx >> 11;
        int w = idx & 2047;
        int r = w >> 4, kc = w & 15;
        const h16* src = (comp ? Qcl : Qch) + qtok + (long)r * 2048 + kc * 8;
        cpa16(smbase + 2u * ((comp ? OQL : OQH) + r * PQ + kc * 8), src);
    }
    // ---- stage 0: Rc hi (2 iters), Hv hi (1 iter) ----
    {
        long rtok = ((long)(b * Sv)) * 2048 + h * 128;
#pragma unroll
        for (int i = 0; i < 2; i++) {
            int idx = tid + i * 512;
            int r = idx >> 4, kc = idx & 15;
            cpa16(smbase + 2u * (ORH + r * PQ + kc * 8), Rch + rtok + (long)r * 2048 + kc * 8);
        }
        {
            int n = tid >> 3, kc = tid & 7;
            cpa16(smbase + 2u * (OHH + n * PH + kc * 8), Hth + zHv + (long)n * 2048 + kc * 8);
        }
        cp_commit();
    }

    uint32_t qadr_h[2], qadr_l[2];
#pragma unroll
    for (int mi = 0; mi < 2; mi++) {
        int rowA = mw * 32 + mi * 16 + (seg & 1) * 8 + sl;
        int colA = (seg >> 1) * 8;
        qadr_h[mi] = smbase + 2u * (OQH + rowA * PQ + colA);
        qadr_l[mi] = smbase + 2u * (OQL + rowA * PQ + colA);
    }
    uint32_t radr;
    {
        int rowB = nw * 16 + (seg >> 1) * 8 + sl;
        int colB = (seg & 1) * 8;
        radr = smbase + 2u * (ORH + rowB * PQ + colB);
    }
    uint32_t hadr[4];
#pragma unroll
    for (int nj = 0; nj < 4; nj++) {
        int rowH = nj * 16 + (seg >> 1) * 8 + sl;
        int colH = (seg & 1) * 8 + nw * 16;
        hadr[nj] = smbase + 2u * (OHH + rowH * PH + colH);
    }

    float U[2][8][4];
#pragma unroll
    for (int mi = 0; mi < 2; mi++)
#pragma unroll
        for (int ni = 0; ni < 8; ni++)
#pragma unroll
            for (int j = 0; j < 4; j++) U[mi][ni][j] = 0.f;
    float sqacc[2][2] = {{0.f, 0.f}, {0.f, 0.f}};

    for (int t = 0; t < NT; t++) {
        if (t + 1 < NT) {
            uint32_t boff = ((t + 1) & 1) * (uint32_t)(STG_E * 2);
            long rtok = ((long)(b * Sv + (t + 1) * 64)) * 2048 + h * 128;
            long hoff = zHv + (t + 1) * 64;
#pragma unroll
            for (int i = 0; i < 2; i++) {
                int idx = tid + i * 512;
                int r = idx >> 4, kc = idx & 15;
                cpa16(smbase + boff + 2u * (ORH + r * PQ + kc * 8),
                      Rch + rtok + (long)r * 2048 + kc * 8);
            }
            {
                int n = tid >> 3, kc = tid & 7;
                cpa16(smbase + boff + 2u * (OHH + n * PH + kc * 8),
                      Hth + hoff + (long)n * 2048 + kc * 8);
            }
            cp_commit();
            cp_wait<1>();
        } else {
            cp_wait<0>();
        }
        __syncthreads();
        uint32_t soff = (t & 1) * (uint32_t)(STG_E * 2);

        // ---- Phase A: S (128q x 64r); warp rows mw*32..+32, cols nw*16..+16
        float sacc[2][2][4];
#pragma unroll
        for (int mi = 0; mi < 2; mi++)
#pragma unroll
            for (int ni = 0; ni < 2; ni++)
#pragma unroll
                for (int j = 0; j < 4; j++) sacc[mi][ni][j] = 0.f;
#pragma unroll
        for (int kk = 0; kk < 8; kk++) {
            uint32_t koff = 32u * kk;
            uint32_t ah[2][4], al[2][4], bh[4];
#pragma unroll
            for (int mi = 0; mi < 2; mi++) {
                ldmx4(ah[mi], qadr_h[mi] + koff);
                ldmx4(al[mi], qadr_l[mi] + koff);
            }
            ldmx4(bh, radr + soff + koff);
#pragma unroll
            for (int mi = 0; mi < 2; mi++)
#pragma unroll
                for (int ni = 0; ni < 2; ni++) {
                    mma_f16(sacc[mi][ni], ah[mi], &bh[ni * 2]);
                    mma_f16(sacc[mi][ni], al[mi], &bh[ni * 2]);
                }
        }
        // ---- sumsq ----
#pragma unroll
        for (int mi = 0; mi < 2; mi++) {
            float s0 = 0.f, s1 = 0.f;
#pragma unroll
            for (int ni = 0; ni < 2; ni++) {
                s0 += sacc[mi][ni][0] * sacc[mi][ni][0] + sacc[mi][ni][1] * sacc[mi][ni][1];
                s1 += sacc[mi][ni][2] * sacc[mi][ni][2] + sacc[mi][ni][3] * sacc[mi][ni][3];
            }
            sqacc[mi][0] += s0; sqacc[mi][1] += s1;
        }
        // ---- Phase B: U += round16(S) @ Hv (warp k-slice = its 16 S-cols)
        uint32_t a2h[2][4];
#pragma unroll
        for (int mi = 0; mi < 2; mi++) {
            a2h[mi][0] = packh2(sacc[mi][0][0], sacc[mi][0][1]);
            a2h[mi][1] = packh2(sacc[mi][0][2], sacc[mi][0][3]);
            a2h[mi][2] = packh2(sacc[mi][1][0], sacc[mi][1][1]);
            a2h[mi][3] = packh2(sacc[mi][1][2], sacc[mi][1][3]);
        }
#pragma unroll
        for (int nj = 0; nj < 4; nj++) {
            uint32_t bh2[4];
            ldmx4(bh2, hadr[nj] + soff);
#pragma unroll
            for (int hf = 0; hf < 2; hf++) {
                int ni = nj * 2 + hf;
#pragma unroll
                for (int mi = 0; mi < 2; mi++)
                    mma_f16(U[mi][ni], a2h[mi], &bh2[hf * 2]);
            }
        }
        __syncthreads();
    }

    // ================= epilogue =================
    float* Ured = (float*)smem_raw;
    float* sq = (float*)(smem_raw + QT * 68 * 4);
    if (tid < QT) sq[tid] = 0.f;
    __syncthreads();
#pragma unroll
    for (int mi = 0; mi < 2; mi++)
#pragma unroll
        for (int hh = 0; hh < 2; hh++) {
            float v = sqacc[mi][hh];
            v += __shfl_xor_sync(0xFFFFFFFF, v, 1);
            v += __shfl_xor_sync(0xFFFFFFFF, v, 2);
            if (tig == 0) atomicAdd(&sq[mw * 32 + mi * 16 + gid + hh * 8], v);
        }
    __syncthreads();
    if (tid < QT) sq[tid] = 1.0f / fmaxf(sqrtf(sq[tid]), NORM_EPS);
    for (int w = 0; w < 4; w++) {
        if (nw == w) {
#pragma unroll
            for (int mi = 0; mi < 2; mi++)
#pragma unroll
                for (int ni = 0; ni < 8; ni++) {
                    int r = mw * 32 + mi * 16 + gid;
                    int c = ni * 8 + tig * 2;
                    if (w == 0) {
                        Ured[r * 68 + c]           = U[mi][ni][0];
                        Ured[r * 68 + c + 1]       = U[mi][ni][1];
                        Ured[(r + 8) * 68 + c]     = U[mi][ni][2];
                        Ured[(r + 8) * 68 + c + 1] = U[mi][ni][3];
                    } else {
                        Ured[r * 68 + c]           += U[mi][ni][0];
                        Ured[r * 68 + c + 1]       += U[mi][ni][1];
                        Ured[(r + 8) * 68 + c]     += U[mi][ni][2];
                        Ured[(r + 8) * 68 + c + 1] += U[mi][ni][3];
                    }
                }
        }
        __syncthreads();
    }
#pragma unroll
    for (int i = 0; i < 4; i++) {
        int idx = tid + i * 512;
        int r = idx >> 4, c4 = (idx & 15) * 4;
        float sc = sq[r];
        float4 v = *(const float4*)(Ured + r * 68 + c4);
        v.x *= sc; v.y *= sc; v.z *= sc; v.w *= sc;
        uint2 hh, ll;
        split4h(v, hh, ll);
        long gpos = ((long)(b * Sv + row0 + r)) * DM + h * 64 + c4;
        *(uint2*)&Aoh[gpos] = hh;
        *(uint2*)&Aol[gpos] = ll;
    }
}

// ===========================================================================
// small kernels
// ===========================================================================
__global__ void split_k(const float* __restrict__ x, h16* __restrict__ h,
                        h16* __restrict__ l, long n4)
{
    long i = (long)blockIdx.x * 256 + threadIdx.x;
    if (i >= n4) return;
    float4 v = *(const float4*)&x[i * 4];
    uint2 hh, ll;
    split4h(v, hh, ll);
    *(uint2*)&h[i * 4] = hh;
    *(uint2*)&l[i * 4] = ll;
}

// transpose + round-to-fp16 (B-side operands: weights, HvT)
__global__ void transpose_round_k(const float* __restrict__ in,
                                  h16* __restrict__ oh,
                                  long ldi, long ldo, int H,
                                  long sIb, long sIh, long sOz)
{
    __shared__ float t[32][33];
    int z = blockIdx.z, b = z / H, h = z - b * H;
    in += (long)b * sIb + (long)h * sIh;
    oh += (long)z * sOz;
    int x0 = blockIdx.x * 32, y0 = blockIdx.y * 32;
    int tx = threadIdx.x & 31, ty = threadIdx.x >> 5;
#pragma unroll
    for (int i = 0; i < 4; i++)
        t[ty + i * 8][tx] = in[(long)(y0 + ty + i * 8) * ldi + x0 + tx];
    __syncthreads();
#pragma unroll
    for (int i = 0; i < 4; i++)
        oh[(long)(x0 + ty + i * 8) * ldo + y0 + tx] = __float2half(t[tx][ty + i * 8]);
}

__global__ void layernorm_split_k(const float* __restrict__ Z,
                                  h16* __restrict__ oh, h16* __restrict__ ol,
                                  const float* __restrict__ g, const float* __restrict__ be)
{
    __shared__ float red[256];
    int tid = threadIdx.x;
    const float* row = Z + (long)blockIdx.x * DL;
    float v[4];
#pragma unroll
    for (int t = 0; t < 4; t++) v[t] = row[tid + t * 256];
    float s = v[0] + v[1] + v[2] + v[3];
    red[tid] = s; __syncthreads();
    for (int off = 128; off > 0; off >>= 1) {
        if (tid < off) red[tid] += red[tid + off];
        __syncthreads();
    }
    float mu = red[0] * (1.0f / DL);
    __syncthreads();
    float vs = 0.f;
#pragma unroll
    for (int t = 0; t < 4; t++) { float d = v[t] - mu; vs += d * d; }
    red[tid] = vs; __syncthreads();
    for (int off = 128; off > 0; off >>= 1) {
        if (tid < off) red[tid] += red[tid + off];
        __syncthreads();
    }
    float rstd = rsqrtf(red[0] * (1.0f / DL) + LN_EPS);
    long base = (long)blockIdx.x * DL;
#pragma unroll
    for (int t = 0; t < 4; t++) {
        int i = tid + t * 256;
        float o = (v[t] - mu) * rstd * g[i] + be[i];
        h16 hv = __float2half(o);
        oh[base + i] = hv;
        ol[base + i] = __float2half(o - __half2float(hv));
    }
}

// phasor for Q and R in one launch (blockIdx.y: 0 = Q split, 1 = R hi-only)
__global__ void phasor2_k(const float* __restrict__ QRH,
                          h16* __restrict__ Qch, h16* __restrict__ Qcl,
                          h16* __restrict__ Rch,
                          const float* __restrict__ Wphi, const float* __restrict__ bphi)
{
    __shared__ float W[HD][HD];
    __shared__ float qrow[4][HD + 4];
    int tid = threadIdx.x;
    int j = tid & 63, g = tid >> 6;
    int which = blockIdx.y;
    for (int i = tid; i < HD * HD; i += 256) W[i >> 6][i & 63] = Wphi[i];
    __syncthreads();
    const float* base = QRH + (long)blockIdx.x * (3 * DM) + (which ? DM : 0);
    h16* oh = which ? Rch : Qch;
    h16* ol = which ? (h16*)nullptr : Qcl;
    long obase = (long)blockIdx.x * (NH * 2 * HD);
    float bj = bphi[j];
    for (int hb = 0; hb < NH; hb += 4) {
        int h = hb + g;
        qrow[g][j] = base[h * HD + j];
        __syncthreads();
        float phi = bj;
#pragma unroll 16
        for (int d = 0; d < HD; d++) phi += qrow[g][d] * W[d][j];
        float q = qrow[g][j];
        float sp, cp;
        sincosf(phi, &sp, &cp);
        float vc = q * cp, vsn = q * sp;
        h16 hc = __float2half(vc), hs = __float2half(vsn);
        long oc = obase + h * 2 * HD + j;
        oh[oc] = hc;
        oh[oc + HD] = hs;
        if (ol) {
            ol[oc] = __float2half(vc - __half2float(hc));
            ol[oc + HD] = __float2half(vsn - __half2float(hs));
        }
        __syncthreads();
    }
}

__global__ void concat3_k(const float* __restrict__ a, const float* __restrict__ b,
                          const float* __restrict__ c, float* __restrict__ o)
{
    int i = blockIdx.x * 256 + threadIdx.x;
    if (i < DM) o[i] = a[i];
    else if (i < 2 * DM) o[i] = b[i - DM];
    else if (i < 3 * DM) o[i] = c[i - 2 * DM];
}

// ===========================================================================
extern "C" void kernel_launch(void* const* d_in, const int* in_sizes, int n_in,
                              void* d_out, int out_size)
{
    const float* query = (const float*)d_in[0];
    const float* Wz   = (const float*)d_in[3];
    const float* bz   = (const float*)d_in[4];
    const float* ln_g = (const float*)d_in[5];
    const float* ln_b = (const float*)d_in[6];
    const float* Wq   = (const float*)d_in[7];
    const float* bq   = (const float*)d_in[8];
    const float* Wr   = (const float*)d_in[9];
    const float* br   = (const float*)d_in[10];
    const float* Wh   = (const float*)d_in[11];
    const float* bh   = (const float*)d_in[12];
    const float* Wphi = (const float*)d_in[13];
    const float* bphi = (const float*)d_in[14];
    const float* Wo   = (const float*)d_in[15];
    const float* bo   = (const float*)d_in[16];
    float* out = (float*)d_out;

    h16 *Qs_h, *Qs_l, *WT_h, *Zs_h, *Zs_l, *Qc_h, *Qc_l, *Rc_h, *HvT_h, *Ao_h, *Ao_l;
    float *Z, *QRH, *bqrh;
    cudaGetSymbolAddress((void**)&Qs_h, g_Qs_h); cudaGetSymbolAddress((void**)&Qs_l, g_Qs_l);
    cudaGetSymbolAddress((void**)&WT_h, g_WT_h);
    cudaGetSymbolAddress((void**)&Z,    g_Z);
    cudaGetSymbolAddress((void**)&Zs_h, g_Zs_h); cudaGetSymbolAddress((void**)&Zs_l, g_Zs_l);
    cudaGetSymbolAddress((void**)&QRH,  g_QRH);
    cudaGetSymbolAddress((void**)&bqrh, g_bqrh);
    cudaGetSymbolAddress((void**)&Qc_h, g_Qc_h); cudaGetSymbolAddress((void**)&Qc_l, g_Qc_l);
    cudaGetSymbolAddress((void**)&Rc_h, g_Rc_h);
    cudaGetSymbolAddress((void**)&HvT_h, g_HvT_h);
    cudaGetSymbolAddress((void**)&Ao_h, g_Ao_h); cudaGetSymbolAddress((void**)&Ao_l, g_Ao_l);

    const int SMG = (2 * 128 + 128) * 72 * 2 * 2;   // 110,592 B
    cudaFuncSetAttribute(gemm_ps, cudaFuncAttributeMaxDynamicSharedMemorySize, SMG);
    cudaFuncSetAttribute(fused_attn_k, cudaFuncAttributeMaxDynamicSharedMemorySize, FA_SMEM);

    dim3 blk(256), gblk(512);
    long szW = (long)DM * DL;

    // 0) transpose+round weights (fp16 hi); split query; combined bias
    transpose_round_k<<<dim3(32, 32, 1), blk>>>(Wz, WT_h + 0 * szW, DL, DM, 1, 0, 0, 0);
    transpose_round_k<<<dim3(32, 32, 1), blk>>>(Wq, WT_h + 1 * szW, DM, DL, 1, 0, 0, 0);
    transpose_round_k<<<dim3(32, 32, 1), blk>>>(Wr, WT_h + 2 * szW, DM, DL, 1, 0, 0, 0);
    transpose_round_k<<<dim3(32, 32, 1), blk>>>(Wh, WT_h + 3 * szW, DM, DL, 1, 0, 0, 0);
    transpose_round_k<<<dim3(32, 32, 1), blk>>>(Wo, WT_h + 4 * szW, DM, DM, 1, 0, 0, 0);
    split_k<<<(TOK * DM / 4 + 255) / 256, blk>>>(query, Qs_h, Qs_l, (long)TOK * DM / 4);
    concat3_k<<<12, blk>>>(bq, br, bh, bqrh);

    // 1) Z = query @ Wz + bz
    gemm_ps<<<dim3(DL / 128, TOK / 128, 1), gblk, SMG>>>(
        Qs_h, Qs_l, WT_h, bz, Z, DM, DM, DM, DL);

    // 2) LayerNorm -> split Zs
    layernorm_split_k<<<TOK, blk>>>(Z, Zs_h, Zs_l, ln_g, ln_b);

    // 3) fused Q|R|H projection (N=3072)
    gemm_ps<<<dim3(3 * DM / 128, TOK / 128, 1), gblk, SMG>>>(
        Zs_h, Zs_l, WT_h + szW, bqrh, QRH, DL, DL, DL, 3 * DM);

    // 4) phasor -> Qc split / Rc hi (one launch)
    phasor2_k<<<dim3(TOK, 2, 1), blk>>>(QRH, Qc_h, Qc_l, Rc_h, Wphi, bphi);

    // 5) Hv^T per (b,h), fp16-rounded (Hv = QRH cols [2048,3072))
    transpose_round_k<<<dim3(HD / 32, Sv / 32, Bv * NH), blk>>>(
        QRH + 2 * DM, HvT_h, 3 * DM, Sv, NH, (long)Sv * 3 * DM, HD, (long)HD * Sv);

    // 6) fused attention -> Ao split
    fused_attn_k<<<dim3(Sv / QT, 1, Bv * NH), gblk, FA_SMEM>>>(
        Qc_h, Qc_l, Rc_h, HvT_h, Ao_h, Ao_l);

    // 7) out = Ao @ Wo + bo
    gemm_ps<<<dim3(DM / 128, TOK / 128, 1), gblk, SMG>>>(
        Ao_h, Ao_l, WT_h + 4 * szW, bo, out, DM, DM, DM, DM);
}

// round 16
// speedup vs baseline: 2.2043x; 1.1150x over previous
#include <cuda_runtime.h>
#include <cuda_fp16.h>
#include <math.h>
#include <stdint.h>

typedef __half h16;

#define Bv 2
#define Sv 2048
#define DM 1024
#define NH 16
#define HD 64
#define DL 1024
#define TOK (Bv*Sv)          // 4096
#define LN_EPS 1e-5f
#define NORM_EPS 1e-12f

// ---- scratch (static device globals; allocation-free) ----
__device__ h16   g_Qs_h[(size_t)TOK * DM],  g_Qs_l[(size_t)TOK * DM];
__device__ h16   g_WT_h[5 * (size_t)DM * DL];                 // weights: hi only
__device__ float g_Z   [(size_t)TOK * DL];
__device__ h16   g_Zs_h[(size_t)TOK * DL],  g_Zs_l[(size_t)TOK * DL];
__device__ float g_QRH [(size_t)TOK * 3 * DM];
__device__ float g_bqrh[3 * DM];
__device__ h16   g_Qc_h[(size_t)TOK * NH * 2 * HD];           // hi only now
__device__ h16   g_Rc_h[(size_t)TOK * NH * 2 * HD];           // hi only
__device__ h16   g_HvT_h[(size_t)Bv * NH * HD * Sv];          // hi only
__device__ h16   g_Ao_h[(size_t)TOK * DM], g_Ao_l[(size_t)TOK * DM];

// ===========================================================================
// helpers
// ===========================================================================
__device__ __forceinline__ uint32_t smem_u32(const void* p) {
    uint32_t a;
    asm("{ .reg .u64 t; cvta.to.shared.u64 t, %1; cvt.u32.u64 %0, t; }"
        : "=r"(a) : "l"(p));
    return a;
}
__device__ __forceinline__ void mma_f16(float* d, const uint32_t* a, const uint32_t* b) {
    asm volatile(
        "mma.sync.aligned.m16n8k16.row.col.f32.f16.f16.f32 "
        "{%0,%1,%2,%3}, {%4,%5,%6,%7}, {%8,%9}, {%0,%1,%2,%3};"
        : "+f"(d[0]), "+f"(d[1]), "+f"(d[2]), "+f"(d[3])
        : "r"(a[0]), "r"(a[1]), "r"(a[2]), "r"(a[3]), "r"(b[0]), "r"(b[1]));
}
__device__ __forceinline__ void ldmx4(uint32_t* r, uint32_t addr) {
    asm volatile("ldmatrix.sync.aligned.m8n8.x4.shared.b16 {%0,%1,%2,%3}, [%4];"
                 : "=r"(r[0]), "=r"(r[1]), "=r"(r[2]), "=r"(r[3]) : "r"(addr));
}
__device__ __forceinline__ void cpa16(uint32_t dst, const void* src) {
    asm volatile("cp.async.cg.shared.global [%0], [%1], 16;" :: "r"(dst), "l"(src));
}
__device__ __forceinline__ void cp_commit() { asm volatile("cp.async.commit_group;"); }
template<int N> __device__ __forceinline__ void cp_wait() {
    asm volatile("cp.async.wait_group %0;" :: "n"(N));
}
__device__ __forceinline__ uint32_t packh2(float a, float b) {
    __half2 t = __floats2half2_rn(a, b);
    return *reinterpret_cast<uint32_t*>(&t);
}
__device__ __forceinline__ void split4h(float4 v, uint2& hh, uint2& ll) {
    h16 ax = __float2half(v.x), ay = __float2half(v.y);
    h16 az = __float2half(v.z), aw = __float2half(v.w);
    __half2 h0 = {ax, ay}, h1 = {az, aw};
    hh.x = *reinterpret_cast<uint32_t*>(&h0); hh.y = *reinterpret_cast<uint32_t*>(&h1);
    ll.x = packh2(v.x - __half2float(ax), v.y - __half2float(ay));
    ll.y = packh2(v.z - __half2float(az), v.w - __half2float(aw));
}

// ===========================================================================
// NT GEMM: C = (Ah+Al) @ Bh^T (+bias). A fp16 split, B fp16 rounded. 2 MMAs.
// BM=128, BN=128, BK=64, 512 threads, double-buffered cp.async, ldmatrix
// ===========================================================================
__global__ void __launch_bounds__(512, 1)
gemm_ps(const h16* __restrict__ Ah_, const h16* __restrict__ Al_,
        const h16* __restrict__ Bh_,
        const float* __restrict__ bias, float* __restrict__ Cf,
        int K, long lda, long ldb, long ldc)
{
    constexpr int BM = 128, BN = 128, BK = 64;
    constexpr int PA = 72;
    constexpr int SBUF = (2 * BM + BN) * PA;          // 27648 elems
    constexpr int OAh = 0, OAl = BM * PA, OBh = 2 * BM * PA;
    constexpr int AIT = 4, BIT = 2;
    constexpr int SP = BN + 4;

    extern __shared__ char smem_raw[];
    float* stg = (float*)smem_raw;
    uint32_t smbase = smem_u32(smem_raw);

    int tid = threadIdx.x, wid = tid >> 5, lane = tid & 31;
    int gid = lane >> 2, tig = lane & 3;
    int seg = lane >> 3, sl = lane & 7;
    int wm0 = (wid >> 2) * 32, wn0 = (wid & 3) * 32;

    int row0 = blockIdx.y * BM, col0 = blockIdx.x * BN;
    const h16* AhP = Ah_ + (long)row0 * lda;
    const h16* AlP = Al_ + (long)row0 * lda;
    const h16* BhP = Bh_ + (long)col0 * ldb;

    const h16* asrc[AIT]; uint32_t adst[AIT];
#pragma unroll
    for (int i = 0; i < AIT; i++) {
        int idx = tid + i * 512;
        int lo = idx >= BM * 8;
        int w = idx - lo * BM * 8;
        int r = w >> 3, kc = w & 7;
        asrc[i] = (lo ? AlP : AhP) + (long)r * lda + kc * 8;
        adst[i] = smbase + 2u * ((lo ? OAl : OAh) + r * PA + kc * 8);
    }
    const h16* bsrc[BIT]; uint32_t bdst[BIT];
#pragma unroll
    for (int i = 0; i < BIT; i++) {
        int idx = tid + i * 512;
        int r = idx >> 3, kc = idx & 7;
        bsrc[i] = BhP + (long)r * ldb + kc * 8;
        bdst[i] = smbase + 2u * (OBh + r * PA + kc * 8);
    }

    uint32_t aadr_h[2], aadr_l[2], badr[2];
#pragma unroll
    for (int mi = 0; mi < 2; mi++) {
        int rowA = wm0 + mi * 16 + (seg & 1) * 8 + sl;
        int colA = (seg >> 1) * 8;
        aadr_h[mi] = smbase + 2u * (OAh + rowA * PA + colA);
        aadr_l[mi] = smbase + 2u * (OAl + rowA * PA + colA);
    }
#pragma unroll
    for (int nj = 0; nj < 2; nj++) {
        int rowB = wn0 + nj * 16 + (seg >> 1) * 8 + sl;
        int colB = (seg & 1) * 8;
        badr[nj] = smbase + 2u * (OBh + rowB * PA + colB);
    }

    float acc[2][4][4];
#pragma unroll
    for (int mi = 0; mi < 2; mi++)
#pragma unroll
        for (int ni = 0; ni < 4; ni++)
#pragma unroll
            for (int j = 0; j < 4; j++) acc[mi][ni][j] = 0.f;

    const int NS = K / BK;
    {
#pragma unroll
        for (int i = 0; i < AIT; i++) cpa16(adst[i], asrc[i]);
#pragma unroll
        for (int i = 0; i < BIT; i++) cpa16(bdst[i], bsrc[i]);
        cp_commit();
    }
    for (int s = 0; s < NS; s++) {
        if (s + 1 < NS) {
            long ko = (long)(s + 1) * BK;
            uint32_t boff = ((s + 1) & 1) * (uint32_t)(SBUF * 2);
#pragma unroll
            for (int i = 0; i < AIT; i++) cpa16(adst[i] + boff, asrc[i] + ko);
#pragma unroll
            for (int i = 0; i < BIT; i++) cpa16(bdst[i] + boff, bsrc[i] + ko);
            cp_commit();
            cp_wait<1>();
        } else {
            cp_wait<0>();
        }
        __syncthreads();
        uint32_t soff = (s & 1) * (uint32_t)(SBUF * 2);
#pragma unroll
        for (int kk = 0; kk < 4; kk++) {
            uint32_t off = soff + 32u * kk;
            uint32_t ah[2][4], al[2][4], bh[2][4];
#pragma unroll
            for (int mi = 0; mi < 2; mi++) {
                ldmx4(ah[mi], aadr_h[mi] + off);
                ldmx4(al[mi], aadr_l[mi] + off);
            }
#pragma unroll
            for (int nj = 0; nj < 2; nj++) ldmx4(bh[nj], badr[nj] + off);
#pragma unroll
            for (int mi = 0; mi < 2; mi++)
#pragma unroll
                for (int ni = 0; ni < 4; ni++) {
                    int nj = ni >> 1, hf = (ni & 1) * 2;
                    mma_f16(acc[mi][ni], ah[mi], &bh[nj][hf]);
                    mma_f16(acc[mi][ni], al[mi], &bh[nj][hf]);
                }
        }
        __syncthreads();
    }

#pragma unroll
    for (int mi = 0; mi < 2; mi++)
#pragma unroll
        for (int ni = 0; ni < 4; ni++) {
            int r = wm0 + mi * 16 + gid;
            int c = wn0 + ni * 8 + tig * 2;
            stg[r * SP + c]           = acc[mi][ni][0];
            stg[r * SP + c + 1]       = acc[mi][ni][1];
            stg[(r + 8) * SP + c]     = acc[mi][ni][2];
            stg[(r + 8) * SP + c + 1] = acc[mi][ni][3];
        }
    __syncthreads();
#pragma unroll
    for (int i = 0; i < 8; i++) {
        int idx = tid + i * 512;
        int row = idx >> 5, c4 = (idx & 31) * 4;
        float4 v = *(const float4*)(stg + row * SP + c4);
        int col = col0 + c4;
        if (bias) {
            float4 bv = *(const float4*)&bias[col];
            v.x += bv.x; v.y += bv.y; v.z += bv.z; v.w += bv.w;
        }
        *(float4*)&Cf[(long)(row0 + row) * ldc + col] = v;
    }
}

// ===========================================================================
// Fused attention: per (b,h,q-tile 128): S = Qc@Rc^T (regs), sumsq, U += S@Hv,
// then U / max(||row||,eps) -> Ao split. 512 threads, 16 warps (4m x 4n).
// Phase A: 1 MMA (Qc and Rc both fp16-rounded). Phase B: 1 MMA (S rounded).
// ===========================================================================
#define NT 32            // r-tiles of 64
#define QT 128
#define PQ 136
#define PH 72
#define STG_E (64*PQ + 64*PH)        // 13312 elems per stage
#define ORH 0
#define OHH (64*PQ)
#define OQH (2*STG_E)
#define FA_SMEM ((2*STG_E + QT*PQ) * 2)   // 88,064 bytes

__global__ void __launch_bounds__(512, 1)
fused_attn_k(const h16* __restrict__ Qch,
             const h16* __restrict__ Rch, const h16* __restrict__ Hth,
             h16* __restrict__ Aoh, h16* __restrict__ Aol)
{
    extern __shared__ char smem_raw[];
    uint32_t smbase = smem_u32(smem_raw);

    int tid = threadIdx.x, wid = tid >> 5, lane = tid & 31;
    int gid = lane >> 2, tig = lane & 3;
    int seg = lane >> 3, sl = lane & 7;
    int mw = wid >> 2, nw = wid & 3;

    int qt = blockIdx.x, z = blockIdx.z;
    int b = z >> 4, h = z & 15;
    int row0 = qt * QT;
    long qtok = ((long)(b * Sv + row0)) * 2048 + h * 128;
    long zHv = (long)z * HD * Sv;

    // ---- Qc prologue (hi only, 128 rows x 128 cols) ----
#pragma unroll
    for (int i = 0; i < 4; i++) {
        int idx = tid + i * 512;
        int r = idx >> 4, kc = idx & 15;
        cpa16(smbase + 2u * (OQH + r * PQ + kc * 8), Qch + qtok + (long)r * 2048 + kc * 8);
    }
    // ---- stage 0: Rc hi (2 iters), Hv hi (1 iter) ----
    {
        long rtok = ((long)(b * Sv)) * 2048 + h * 128;
#pragma unroll
        for (int i = 0; i < 2; i++) {
            int idx = tid + i * 512;
            int r = idx >> 4, kc = idx & 15;
            cpa16(smbase + 2u * (ORH + r * PQ + kc * 8), Rch + rtok + (long)r * 2048 + kc * 8);
        }
        {
            int n = tid >> 3, kc = tid & 7;
            cpa16(smbase + 2u * (OHH + n * PH + kc * 8), Hth + zHv + (long)n * 2048 + kc * 8);
        }
        cp_commit();
    }

    uint32_t qadr[2];
#pragma unroll
    for (int mi = 0; mi < 2; mi++) {
        int rowA = mw * 32 + mi * 16 + (seg & 1) * 8 + sl;
        int colA = (seg >> 1) * 8;
        qadr[mi] = smbase + 2u * (OQH + rowA * PQ + colA);
    }
    uint32_t radr;
    {
        int rowB = nw * 16 + (seg >> 1) * 8 + sl;
        int colB = (seg & 1) * 8;
        radr = smbase + 2u * (ORH + rowB * PQ + colB);
    }
    uint32_t hadr[4];
#pragma unroll
    for (int nj = 0; nj < 4; nj++) {
        int rowH = nj * 16 + (seg >> 1) * 8 + sl;
        int colH = (seg & 1) * 8 + nw * 16;
        hadr[nj] = smbase + 2u * (OHH + rowH * PH + colH);
    }

    float U[2][8][4];
#pragma unroll
    for (int mi = 0; mi < 2; mi++)
#pragma unroll
        for (int ni = 0; ni < 8; ni++)
#pragma unroll
            for (int j = 0; j < 4; j++) U[mi][ni][j] = 0.f;
    float sqacc[2][2] = {{0.f, 0.f}, {0.f, 0.f}};

    for (int t = 0; t < NT; t++) {
        if (t + 1 < NT) {
            uint32_t boff = ((t + 1) & 1) * (uint32_t)(STG_E * 2);
            long rtok = ((long)(b * Sv + (t + 1) * 64)) * 2048 + h * 128;
            long hoff = zHv + (t + 1) * 64;
#pragma unroll
            for (int i = 0; i < 2; i++) {
                int idx = tid + i * 512;
                int r = idx >> 4, kc = idx & 15;
                cpa16(smbase + boff + 2u * (ORH + r * PQ + kc * 8),
                      Rch + rtok + (long)r * 2048 + kc * 8);
            }
            {
                int n = tid >> 3, kc = tid & 7;
                cpa16(smbase + boff + 2u * (OHH + n * PH + kc * 8),
                      Hth + hoff + (long)n * 2048 + kc * 8);
            }
            cp_commit();
            cp_wait<1>();
        } else {
            cp_wait<0>();
        }
        __syncthreads();
        uint32_t soff = (t & 1) * (uint32_t)(STG_E * 2);

        // ---- Phase A: S (128q x 64r); warp rows mw*32..+32, cols nw*16..+16
        float sacc[2][2][4];
#pragma unroll
        for (int mi = 0; mi < 2; mi++)
#pragma unroll
            for (int ni = 0; ni < 2; ni++)
#pragma unroll
                for (int j = 0; j < 4; j++) sacc[mi][ni][j] = 0.f;
#pragma unroll
        for (int kk = 0; kk < 8; kk++) {
            uint32_t koff = 32u * kk;
            uint32_t ah[2][4], bh[4];
#pragma unroll
            for (int mi = 0; mi < 2; mi++) ldmx4(ah[mi], qadr[mi] + koff);
            ldmx4(bh, radr + soff + koff);
#pragma unroll
            for (int mi = 0; mi < 2; mi++)
#pragma unroll
                for (int ni = 0; ni < 2; ni++)
                    mma_f16(sacc[mi][ni], ah[mi], &bh[ni * 2]);
        }
        // ---- sumsq ----
#pragma unroll
        for (int mi = 0; mi < 2; mi++) {
            float s0 = 0.f, s1 = 0.f;
#pragma unroll
            for (int ni = 0; ni < 2; ni++) {
                s0 += sacc[mi][ni][0] * sacc[mi][ni][0] + sacc[mi][ni][1] * sacc[mi][ni][1];
                s1 += sacc[mi][ni][2] * sacc[mi][ni][2] + sacc[mi][ni][3] * sacc[mi][ni][3];
            }
            sqacc[mi][0] += s0; sqacc[mi][1] += s1;
        }
        // ---- Phase B: U += round16(S) @ Hv (warp k-slice = its 16 S-cols)
        uint32_t a2h[2][4];
#pragma unroll
        for (int mi = 0; mi < 2; mi++) {
            a2h[mi][0] = packh2(sacc[mi][0][0], sacc[mi][0][1]);
            a2h[mi][1] = packh2(sacc[mi][0][2], sacc[mi][0][3]);
            a2h[mi][2] = packh2(sacc[mi][1][0], sacc[mi][1][1]);
            a2h[mi][3] = packh2(sacc[mi][1][2], sacc[mi][1][3]);
        }
#pragma unroll
        for (int nj = 0; nj < 4; nj++) {
            uint32_t bh2[4];
            ldmx4(bh2, hadr[nj] + soff);
#pragma unroll
            for (int hf = 0; hf < 2; hf++) {
                int ni = nj * 2 + hf;
#pragma unroll
                for (int mi = 0; mi < 2; mi++)
                    mma_f16(U[mi][ni], a2h[mi], &bh2[hf * 2]);
            }
        }
        __syncthreads();
    }

    // ================= epilogue =================
    float* Ured = (float*)smem_raw;
    float* sq = (float*)(smem_raw + QT * 68 * 4);
    if (tid < QT) sq[tid] = 0.f;
    __syncthreads();
#pragma unroll
    for (int mi = 0; mi < 2; mi++)
#pragma unroll
        for (int hh = 0; hh < 2; hh++) {
            float v = sqacc[mi][hh];
            v += __shfl_xor_sync(0xFFFFFFFF, v, 1);
            v += __shfl_xor_sync(0xFFFFFFFF, v, 2);
            if (tig == 0) atomicAdd(&sq[mw * 32 + mi * 16 + gid + hh * 8], v);
        }
    __syncthreads();
    if (tid < QT) sq[tid] = 1.0f / fmaxf(sqrtf(sq[tid]), NORM_EPS);
    for (int w = 0; w < 4; w++) {
        if (nw == w) {
#pragma unroll
            for (int mi = 0; mi < 2; mi++)
#pragma unroll
                for (int ni = 0; ni < 8; ni++) {
                    int r = mw * 32 + mi * 16 + gid;
                    int c = ni * 8 + tig * 2;
                    if (w == 0) {
                        Ured[r * 68 + c]           = U[mi][ni][0];
                        Ured[r * 68 + c + 1]       = U[mi][ni][1];
                        Ured[(r + 8) * 68 + c]     = U[mi][ni][2];
                        Ured[(r + 8) * 68 + c + 1] = U[mi][ni][3];
                    } else {
                        Ured[r * 68 + c]           += U[mi][ni][0];
                        Ured[r * 68 + c + 1]       += U[mi][ni][1];
                        Ured[(r + 8) * 68 + c]     += U[mi][ni][2];
                        Ured[(r + 8) * 68 + c + 1] += U[mi][ni][3];
                    }
                }
        }
        __syncthreads();
    }
#pragma unroll
    for (int i = 0; i < 4; i++) {
        int idx = tid + i * 512;
        int r = idx >> 4, c4 = (idx & 15) * 4;
        float sc = sq[r];
        float4 v = *(const float4*)(Ured + r * 68 + c4);
        v.x *= sc; v.y *= sc; v.z *= sc; v.w *= sc;
        uint2 hh, ll;
        split4h(v, hh, ll);
        long gpos = ((long)(b * Sv + row0 + r)) * DM + h * 64 + c4;
        *(uint2*)&Aoh[gpos] = hh;
        *(uint2*)&Aol[gpos] = ll;
    }
}

// ===========================================================================
// small kernels
// ===========================================================================
__global__ void split_k(const float* __restrict__ x, h16* __restrict__ h,
                        h16* __restrict__ l, long n4)
{
    long i = (long)blockIdx.x * 256 + threadIdx.x;
    if (i >= n4) return;
    float4 v = *(const float4*)&x[i * 4];
    uint2 hh, ll;
    split4h(v, hh, ll);
    *(uint2*)&h[i * 4] = hh;
    *(uint2*)&l[i * 4] = ll;
}

// transpose + round-to-fp16 (B-side operands: weights, HvT)
__global__ void transpose_round_k(const float* __restrict__ in,
                                  h16* __restrict__ oh,
                                  long ldi, long ldo, int H,
                                  long sIb, long sIh, long sOz)
{
    __shared__ float t[32][33];
    int z = blockIdx.z, b = z / H, h = z - b * H;
    in += (long)b * sIb + (long)h * sIh;
    oh += (long)z * sOz;
    int x0 = blockIdx.x * 32, y0 = blockIdx.y * 32;
    int tx = threadIdx.x & 31, ty = threadIdx.x >> 5;
#pragma unroll
    for (int i = 0; i < 4; i++)
        t[ty + i * 8][tx] = in[(long)(y0 + ty + i * 8) * ldi + x0 + tx];
    __syncthreads();
#pragma unroll
    for (int i = 0; i < 4; i++)
        oh[(long)(x0 + ty + i * 8) * ldo + y0 + tx] = __float2half(t[tx][ty + i * 8]);
}

__global__ void layernorm_split_k(const float* __restrict__ Z,
                                  h16* __restrict__ oh, h16* __restrict__ ol,
                                  const float* __restrict__ g, const float* __restrict__ be)
{
    __shared__ float red[256];
    int tid = threadIdx.x;
    const float* row = Z + (long)blockIdx.x * DL;
    float v[4];
#pragma unroll
    for (int t = 0; t < 4; t++) v[t] = row[tid + t * 256];
    float s = v[0] + v[1] + v[2] + v[3];
    red[tid] = s; __syncthreads();
    for (int off = 128; off > 0; off >>= 1) {
        if (tid < off) red[tid] += red[tid + off];
        __syncthreads();
    }
    float mu = red[0] * (1.0f / DL);
    __syncthreads();
    float vs = 0.f;
#pragma unroll
    for (int t = 0; t < 4; t++) { float d = v[t] - mu; vs += d * d; }
    red[tid] = vs; __syncthreads();
    for (int off = 128; off > 0; off >>= 1) {
        if (tid < off) red[tid] += red[tid + off];
        __syncthreads();
    }
    float rstd = rsqrtf(red[0] * (1.0f / DL) + LN_EPS);
    long base = (long)blockIdx.x * DL;
#pragma unroll
    for (int t = 0; t < 4; t++) {
        int i = tid + t * 256;
        float o = (v[t] - mu) * rstd * g[i] + be[i];
        h16 hv = __float2half(o);
        oh[base + i] = hv;
        ol[base + i] = __float2half(o - __half2float(hv));
    }
}

// phasor for Q and R in one launch (hi-only outputs for both now)
__global__ void phasor2_k(const float* __restrict__ QRH,
                          h16* __restrict__ Qch, h16* __restrict__ Rch,
                          const float* __restrict__ Wphi, const float* __restrict__ bphi)
{
    __shared__ float W[HD][HD];
    __shared__ float qrow[4][HD + 4];
    int tid = threadIdx.x;
    int j = tid & 63, g = tid >> 6;
    int which = blockIdx.y;
    for (int i = tid; i < HD * HD; i += 256) W[i >> 6][i & 63] = Wphi[i];
    __syncthreads();
    const float* base = QRH + (long)blockIdx.x * (3 * DM) + (which ? DM : 0);
    h16* oh = which ? Rch : Qch;
    long obase = (long)blockIdx.x * (NH * 2 * HD);
    float bj = bphi[j];
    for (int hb = 0; hb < NH; hb += 4) {
        int h = hb + g;
        qrow[g][j] = base[h * HD + j];
        __syncthreads();
        float phi = bj;
#pragma unroll 16
        for (int d = 0; d < HD; d++) phi += qrow[g][d] * W[d][j];
        float q = qrow[g][j];
        float sp, cp;
        sincosf(phi, &sp, &cp);
        long oc = obase + h * 2 * HD + j;
        oh[oc]      = __float2half(q * cp);
        oh[oc + HD] = __float2half(q * sp);
        __syncthreads();
    }
}

__global__ void concat3_k(const float* __restrict__ a, const float* __restrict__ b,
                          const float* __restrict__ c, float* __restrict__ o)
{
    int i = blockIdx.x * 256 + threadIdx.x;
    if (i < DM) o[i] = a[i];
    else if (i < 2 * DM) o[i] = b[i - DM];
    else if (i < 3 * DM) o[i] = c[i - 2 * DM];
}

// ===========================================================================
extern "C" void kernel_launch(void* const* d_in, const int* in_sizes, int n_in,
                              void* d_out, int out_size)
{
    const float* query = (const float*)d_in[0];
    const float* Wz   = (const float*)d_in[3];
    const float* bz   = (const float*)d_in[4];
    const float* ln_g = (const float*)d_in[5];
    const float* ln_b = (const float*)d_in[6];
    const float* Wq   = (const float*)d_in[7];
    const float* bq   = (const float*)d_in[8];
    const float* Wr   = (const float*)d_in[9];
    const float* br   = (const float*)d_in[10];
    const float* Wh   = (const float*)d_in[11];
    const float* bh   = (const float*)d_in[12];
    const float* Wphi = (const float*)d_in[13];
    const float* bphi = (const float*)d_in[14];
    const float* Wo   = (const float*)d_in[15];
    const float* bo   = (const float*)d_in[16];
    float* out = (float*)d_out;

    h16 *Qs_h, *Qs_l, *WT_h, *Zs_h, *Zs_l, *Qc_h, *Rc_h, *HvT_h, *Ao_h, *Ao_l;
    float *Z, *QRH, *bqrh;
    cudaGetSymbolAddress((void**)&Qs_h, g_Qs_h); cudaGetSymbolAddress((void**)&Qs_l, g_Qs_l);
    cudaGetSymbolAddress((void**)&WT_h, g_WT_h);
    cudaGetSymbolAddress((void**)&Z,    g_Z);
    cudaGetSymbolAddress((void**)&Zs_h, g_Zs_h); cudaGetSymbolAddress((void**)&Zs_l, g_Zs_l);
    cudaGetSymbolAddress((void**)&QRH,  g_QRH);
    cudaGetSymbolAddress((void**)&bqrh, g_bqrh);
    cudaGetSymbolAddress((void**)&Qc_h, g_Qc_h);
    cudaGetSymbolAddress((void**)&Rc_h, g_Rc_h);
    cudaGetSymbolAddress((void**)&HvT_h, g_HvT_h);
    cudaGetSymbolAddress((void**)&Ao_h, g_Ao_h); cudaGetSymbolAddress((void**)&Ao_l, g_Ao_l);

    const int SMG = (2 * 128 + 128) * 72 * 2 * 2;   // 110,592 B
    cudaFuncSetAttribute(gemm_ps, cudaFuncAttributeMaxDynamicSharedMemorySize, SMG);
    cudaFuncSetAttribute(fused_attn_k, cudaFuncAttributeMaxDynamicSharedMemorySize, FA_SMEM);

    dim3 blk(256), gblk(512);
    long szW = (long)DM * DL;

    // 0) transpose+round weights (fp16 hi); split query; combined bias
    transpose_round_k<<<dim3(32, 32, 1), blk>>>(Wz, WT_h + 0 * szW, DL, DM, 1, 0, 0, 0);
    transpose_round_k<<<dim3(32, 32, 1), blk>>>(Wq, WT_h + 1 * szW, DM, DL, 1, 0, 0, 0);
    transpose_round_k<<<dim3(32, 32, 1), blk>>>(Wr, WT_h + 2 * szW, DM, DL, 1, 0, 0, 0);
    transpose_round_k<<<dim3(32, 32, 1), blk>>>(Wh, WT_h + 3 * szW, DM, DL, 1, 0, 0, 0);
    transpose_round_k<<<dim3(32, 32, 1), blk>>>(Wo, WT_h + 4 * szW, DM, DM, 1, 0, 0, 0);
    split_k<<<(TOK * DM / 4 + 255) / 256, blk>>>(query, Qs_h, Qs_l, (long)TOK * DM / 4);
    concat3_k<<<12, blk>>>(bq, br, bh, bqrh);

    // 1) Z = query @ Wz + bz
    gemm_ps<<<dim3(DL / 128, TOK / 128, 1), gblk, SMG>>>(
        Qs_h, Qs_l, WT_h, bz, Z, DM, DM, DM, DL);

    // 2) LayerNorm -> split Zs
    layernorm_split_k<<<TOK, blk>>>(Z, Zs_h, Zs_l, ln_g, ln_b);

    // 3) fused Q|R|H projection (N=3072)
    gemm_ps<<<dim3(3 * DM / 128, TOK / 128, 1), gblk, SMG>>>(
        Zs_h, Zs_l, WT_h + szW, bqrh, QRH, DL, DL, DL, 3 * DM);

    // 4) phasor -> Qc hi / Rc hi (one launch)
    phasor2_k<<<dim3(TOK, 2, 1), blk>>>(QRH, Qc_h, Rc_h, Wphi, bphi);

    // 5) Hv^T per (b,h), fp16-rounded (Hv = QRH cols [2048,3072))
    transpose_round_k<<<dim3(HD / 32, Sv / 32, Bv * NH), blk>>>(
        QRH + 2 * DM, HvT_h, 3 * DM, Sv, NH, (long)Sv * 3 * DM, HD, (long)HD * Sv);

    // 6) fused attention -> Ao split
    fused_attn_k<<<dim3(Sv / QT, 1, Bv * NH), gblk, FA_SMEM>>>(
        Qc_h, Rc_h, HvT_h, Ao_h, Ao_l);

    // 7) out = Ao @ Wo + bo
    gemm_ps<<<dim3(DM / 128, TOK / 128, 1), gblk, SMG>>>(
        Ao_h, Ao_l, WT_h + 4 * szW, bo, out, DM, DM, DM, DM);
}

// round 17
// speedup vs baseline: 2.6239x; 1.1904x over previous
#include <cuda_runtime.h>
#include <cuda_fp16.h>
#include <math.h>
#include <stdint.h>

typedef __half h16;

#define Bv 2
#define Sv 2048
#define DM 1024
#define NH 16
#define HD 64
#define DL 1024
#define TOK (Bv*Sv)          // 4096
#define LN_EPS 1e-5f
#define NORM_EPS 1e-12f

// ---- scratch (static device globals; allocation-free) ----
__device__ h16   g_Qs_h[(size_t)TOK * DM];                    // query fp16
__device__ h16   g_WT_h[5 * (size_t)DM * DL];                 // weights fp16 (transposed)
__device__ float g_Z   [(size_t)TOK * DL];
__device__ h16   g_Zs_h[(size_t)TOK * DL];                    // LN out fp16
__device__ float g_QRH [(size_t)TOK * 3 * DM];
__device__ float g_bqrh[3 * DM];
__device__ h16   g_Qc_h[(size_t)TOK * NH * 2 * HD];
__device__ h16   g_Rc_h[(size_t)TOK * NH * 2 * HD];
__device__ h16   g_HvT_h[(size_t)Bv * NH * HD * Sv];
__device__ h16   g_Ao_h[(size_t)TOK * DM];

// ===========================================================================
// helpers
// ===========================================================================
__device__ __forceinline__ uint32_t smem_u32(const void* p) {
    uint32_t a;
    asm("{ .reg .u64 t; cvta.to.shared.u64 t, %1; cvt.u32.u64 %0, t; }"
        : "=r"(a) : "l"(p));
    return a;
}
__device__ __forceinline__ void mma_f16(float* d, const uint32_t* a, const uint32_t* b) {
    asm volatile(
        "mma.sync.aligned.m16n8k16.row.col.f32.f16.f16.f32 "
        "{%0,%1,%2,%3}, {%4,%5,%6,%7}, {%8,%9}, {%0,%1,%2,%3};"
        : "+f"(d[0]), "+f"(d[1]), "+f"(d[2]), "+f"(d[3])
        : "r"(a[0]), "r"(a[1]), "r"(a[2]), "r"(a[3]), "r"(b[0]), "r"(b[1]));
}
__device__ __forceinline__ void ldmx4(uint32_t* r, uint32_t addr) {
    asm volatile("ldmatrix.sync.aligned.m8n8.x4.shared.b16 {%0,%1,%2,%3}, [%4];"
                 : "=r"(r[0]), "=r"(r[1]), "=r"(r[2]), "=r"(r[3]) : "r"(addr));
}
__device__ __forceinline__ void cpa16(uint32_t dst, const void* src) {
    asm volatile("cp.async.cg.shared.global [%0], [%1], 16;" :: "r"(dst), "l"(src));
}
__device__ __forceinline__ void cp_commit() { asm volatile("cp.async.commit_group;"); }
template<int N> __device__ __forceinline__ void cp_wait() {
    asm volatile("cp.async.wait_group %0;" :: "n"(N));
}
__device__ __forceinline__ uint32_t packh2(float a, float b) {
    __half2 t = __floats2half2_rn(a, b);
    return *reinterpret_cast<uint32_t*>(&t);
}

// ===========================================================================
// NT GEMM, pure fp16: C = Ah @ Bh^T (+bias). 1 MMA per fragment.
// BM=128, BN=128, BK=64, 512 threads, double-buffered cp.async, ldmatrix
// ===========================================================================
__global__ void __launch_bounds__(512, 1)
gemm_ps(const h16* __restrict__ Ah_, const h16* __restrict__ Bh_,
        const float* __restrict__ bias, float* __restrict__ Cf,
        int K, long lda, long ldb, long ldc)
{
    constexpr int BM = 128, BN = 128, BK = 64;
    constexpr int PA = 72;
    constexpr int SBUF = (BM + BN) * PA;              // 18432 elems / stage
    constexpr int OAh = 0, OBh = BM * PA;
    constexpr int SP = BN + 4;

    extern __shared__ char smem_raw[];
    float* stg = (float*)smem_raw;
    uint32_t smbase = smem_u32(smem_raw);

    int tid = threadIdx.x, wid = tid >> 5, lane = tid & 31;
    int gid = lane >> 2, tig = lane & 3;
    int seg = lane >> 3, sl = lane & 7;
    int wm0 = (wid >> 2) * 32, wn0 = (wid & 3) * 32;

    int row0 = blockIdx.y * BM, col0 = blockIdx.x * BN;
    const h16* AhP = Ah_ + (long)row0 * lda;
    const h16* BhP = Bh_ + (long)col0 * ldb;

    const h16* asrc[2]; uint32_t adst[2];
#pragma unroll
    for (int i = 0; i < 2; i++) {
        int idx = tid + i * 512;
        int r = idx >> 3, kc = idx & 7;
        asrc[i] = AhP + (long)r * lda + kc * 8;
        adst[i] = smbase + 2u * (OAh + r * PA + kc * 8);
    }
    const h16* bsrc[2]; uint32_t bdst[2];
#pragma unroll
    for (int i = 0; i < 2; i++) {
        int idx = tid + i * 512;
        int r = idx >> 3, kc = idx & 7;
        bsrc[i] = BhP + (long)r * ldb + kc * 8;
        bdst[i] = smbase + 2u * (OBh + r * PA + kc * 8);
    }

    uint32_t aadr[2], badr[2];
#pragma unroll
    for (int mi = 0; mi < 2; mi++) {
        int rowA = wm0 + mi * 16 + (seg & 1) * 8 + sl;
        int colA = (seg >> 1) * 8;
        aadr[mi] = smbase + 2u * (OAh + rowA * PA + colA);
    }
#pragma unroll
    for (int nj = 0; nj < 2; nj++) {
        int rowB = wn0 + nj * 16 + (seg >> 1) * 8 + sl;
        int colB = (seg & 1) * 8;
        badr[nj] = smbase + 2u * (OBh + rowB * PA + colB);
    }

    float acc[2][4][4];
#pragma unroll
    for (int mi = 0; mi < 2; mi++)
#pragma unroll
        for (int ni = 0; ni < 4; ni++)
#pragma unroll
            for (int j = 0; j < 4; j++) acc[mi][ni][j] = 0.f;

    const int NS = K / BK;
    {
#pragma unroll
        for (int i = 0; i < 2; i++) cpa16(adst[i], asrc[i]);
#pragma unroll
        for (int i = 0; i < 2; i++) cpa16(bdst[i], bsrc[i]);
        cp_commit();
    }
    for (int s = 0; s < NS; s++) {
        if (s + 1 < NS) {
            long ko = (long)(s + 1) * BK;
            uint32_t boff = ((s + 1) & 1) * (uint32_t)(SBUF * 2);
#pragma unroll
            for (int i = 0; i < 2; i++) cpa16(adst[i] + boff, asrc[i] + ko);
#pragma unroll
            for (int i = 0; i < 2; i++) cpa16(bdst[i] + boff, bsrc[i] + ko);
            cp_commit();
            cp_wait<1>();
        } else {
            cp_wait<0>();
        }
        __syncthreads();
        uint32_t soff = (s & 1) * (uint32_t)(SBUF * 2);
#pragma unroll
        for (int kk = 0; kk < 4; kk++) {
            uint32_t off = soff + 32u * kk;
            uint32_t ah[2][4], bh[2][4];
#pragma unroll
            for (int mi = 0; mi < 2; mi++) ldmx4(ah[mi], aadr[mi] + off);
#pragma unroll
            for (int nj = 0; nj < 2; nj++) ldmx4(bh[nj], badr[nj] + off);
#pragma unroll
            for (int mi = 0; mi < 2; mi++)
#pragma unroll
                for (int ni = 0; ni < 4; ni++) {
                    int nj = ni >> 1, hf = (ni & 1) * 2;
                    mma_f16(acc[mi][ni], ah[mi], &bh[nj][hf]);
                }
        }
        __syncthreads();
    }

#pragma unroll
    for (int mi = 0; mi < 2; mi++)
#pragma unroll
        for (int ni = 0; ni < 4; ni++) {
            int r = wm0 + mi * 16 + gid;
            int c = wn0 + ni * 8 + tig * 2;
            stg[r * SP + c]           = acc[mi][ni][0];
            stg[r * SP + c + 1]       = acc[mi][ni][1];
            stg[(r + 8) * SP + c]     = acc[mi][ni][2];
            stg[(r + 8) * SP + c + 1] = acc[mi][ni][3];
        }
    __syncthreads();
#pragma unroll
    for (int i = 0; i < 8; i++) {
        int idx = tid + i * 512;
        int row = idx >> 5, c4 = (idx & 31) * 4;
        float4 v = *(const float4*)(stg + row * SP + c4);
        int col = col0 + c4;
        if (bias) {
            float4 bv = *(const float4*)&bias[col];
            v.x += bv.x; v.y += bv.y; v.z += bv.z; v.w += bv.w;
        }
        *(float4*)&Cf[(long)(row0 + row) * ldc + col] = v;
    }
}

// ===========================================================================
// Fused attention: per (b,h,q-tile 128): S = Qc@Rc^T (regs), sumsq, U += S@Hv,
// then U / max(||row||,eps) -> Ao (fp16). 512 threads, 16 warps (4m x 4n).
// All operands fp16-rounded: Phase A 1 MMA, Phase B 1 MMA.
// ===========================================================================
#define NT 32            // r-tiles of 64
#define QT 128
#define PQ 136
#define PH 72
#define STG_E (64*PQ + 64*PH)        // 13312 elems per stage
#define ORH 0
#define OHH (64*PQ)
#define OQH (2*STG_E)
#define FA_SMEM ((2*STG_E + QT*PQ) * 2)   // 88,064 bytes

__global__ void __launch_bounds__(512, 1)
fused_attn_k(const h16* __restrict__ Qch,
             const h16* __restrict__ Rch, const h16* __restrict__ Hth,
             h16* __restrict__ Aoh)
{
    extern __shared__ char smem_raw[];
    uint32_t smbase = smem_u32(smem_raw);

    int tid = threadIdx.x, wid = tid >> 5, lane = tid & 31;
    int gid = lane >> 2, tig = lane & 3;
    int seg = lane >> 3, sl = lane & 7;
    int mw = wid >> 2, nw = wid & 3;

    int qt = blockIdx.x, z = blockIdx.z;
    int b = z >> 4, h = z & 15;
    int row0 = qt * QT;
    long qtok = ((long)(b * Sv + row0)) * 2048 + h * 128;
    long zHv = (long)z * HD * Sv;

    // ---- Qc prologue (hi only, 128 rows x 128 cols) ----
#pragma unroll
    for (int i = 0; i < 4; i++) {
        int idx = tid + i * 512;
        int r = idx >> 4, kc = idx & 15;
        cpa16(smbase + 2u * (OQH + r * PQ + kc * 8), Qch + qtok + (long)r * 2048 + kc * 8);
    }
    // ---- stage 0: Rc (2 iters), Hv (1 iter) ----
    {
        long rtok = ((long)(b * Sv)) * 2048 + h * 128;
#pragma unroll
        for (int i = 0; i < 2; i++) {
            int idx = tid + i * 512;
            int r = idx >> 4, kc = idx & 15;
            cpa16(smbase + 2u * (ORH + r * PQ + kc * 8), Rch + rtok + (long)r * 2048 + kc * 8);
        }
        {
            int n = tid >> 3, kc = tid & 7;
            cpa16(smbase + 2u * (OHH + n * PH + kc * 8), Hth + zHv + (long)n * 2048 + kc * 8);
        }
        cp_commit();
    }

    uint32_t qadr[2];
#pragma unroll
    for (int mi = 0; mi < 2; mi++) {
        int rowA = mw * 32 + mi * 16 + (seg & 1) * 8 + sl;
        int colA = (seg >> 1) * 8;
        qadr[mi] = smbase + 2u * (OQH + rowA * PQ + colA);
    }
    uint32_t radr;
    {
        int rowB = nw * 16 + (seg >> 1) * 8 + sl;
        int colB = (seg & 1) * 8;
        radr = smbase + 2u * (ORH + rowB * PQ + colB);
    }
    uint32_t hadr[4];
#pragma unroll
    for (int nj = 0; nj < 4; nj++) {
        int rowH = nj * 16 + (seg >> 1) * 8 + sl;
        int colH = (seg & 1) * 8 + nw * 16;
        hadr[nj] = smbase + 2u * (OHH + rowH * PH + colH);
    }

    float U[2][8][4];
#pragma unroll
    for (int mi = 0; mi < 2; mi++)
#pragma unroll
        for (int ni = 0; ni < 8; ni++)
#pragma unroll
            for (int j = 0; j < 4; j++) U[mi][ni][j] = 0.f;
    float sqacc[2][2] = {{0.f, 0.f}, {0.f, 0.f}};

    for (int t = 0; t < NT; t++) {
        if (t + 1 < NT) {
            uint32_t boff = ((t + 1) & 1) * (uint32_t)(STG_E * 2);
            long rtok = ((long)(b * Sv + (t + 1) * 64)) * 2048 + h * 128;
            long hoff = zHv + (t + 1) * 64;
#pragma unroll
            for (int i = 0; i < 2; i++) {
                int idx = tid + i * 512;
                int r = idx >> 4, kc = idx & 15;
                cpa16(smbase + boff + 2u * (ORH + r * PQ + kc * 8),
                      Rch + rtok + (long)r * 2048 + kc * 8);
            }
            {
                int n = tid >> 3, kc = tid & 7;
                cpa16(smbase + boff + 2u * (OHH + n * PH + kc * 8),
                      Hth + hoff + (long)n * 2048 + kc * 8);
            }
            cp_commit();
            cp_wait<1>();
        } else {
            cp_wait<0>();
        }
        __syncthreads();
        uint32_t soff = (t & 1) * (uint32_t)(STG_E * 2);

        // ---- Phase A: S (128q x 64r)
        float sacc[2][2][4];
#pragma unroll
        for (int mi = 0; mi < 2; mi++)
#pragma unroll
            for (int ni = 0; ni < 2; ni++)
#pragma unroll
                for (int j = 0; j < 4; j++) sacc[mi][ni][j] = 0.f;
#pragma unroll
        for (int kk = 0; kk < 8; kk++) {
            uint32_t koff = 32u * kk;
            uint32_t ah[2][4], bh[4];
#pragma unroll
            for (int mi = 0; mi < 2; mi++) ldmx4(ah[mi], qadr[mi] + koff);
            ldmx4(bh, radr + soff + koff);
#pragma unroll
            for (int mi = 0; mi < 2; mi++)
#pragma unroll
                for (int ni = 0; ni < 2; ni++)
                    mma_f16(sacc[mi][ni], ah[mi], &bh[ni * 2]);
        }
        // ---- sumsq ----
#pragma unroll
        for (int mi = 0; mi < 2; mi++) {
            float s0 = 0.f, s1 = 0.f;
#pragma unroll
            for (int ni = 0; ni < 2; ni++) {
                s0 += sacc[mi][ni][0] * sacc[mi][ni][0] + sacc[mi][ni][1] * sacc[mi][ni][1];
                s1 += sacc[mi][ni][2] * sacc[mi][ni][2] + sacc[mi][ni][3] * sacc[mi][ni][3];
            }
            sqacc[mi][0] += s0; sqacc[mi][1] += s1;
        }
        // ---- Phase B: U += round16(S) @ Hv
        uint32_t a2h[2][4];
#pragma unroll
        for (int mi = 0; mi < 2; mi++) {
            a2h[mi][0] = packh2(sacc[mi][0][0], sacc[mi][0][1]);
            a2h[mi][1] = packh2(sacc[mi][0][2], sacc[mi][0][3]);
            a2h[mi][2] = packh2(sacc[mi][1][0], sacc[mi][1][1]);
            a2h[mi][3] = packh2(sacc[mi][1][2], sacc[mi][1][3]);
        }
#pragma unroll
        for (int nj = 0; nj < 4; nj++) {
            uint32_t bh2[4];
            ldmx4(bh2, hadr[nj] + soff);
#pragma unroll
            for (int hf = 0; hf < 2; hf++) {
                int ni = nj * 2 + hf;
#pragma unroll
                for (int mi = 0; mi < 2; mi++)
                    mma_f16(U[mi][ni], a2h[mi], &bh2[hf * 2]);
            }
        }
        __syncthreads();
    }

    // ================= epilogue =================
    float* Ured = (float*)smem_raw;
    float* sq = (float*)(smem_raw + QT * 68 * 4);
    if (tid < QT) sq[tid] = 0.f;
    __syncthreads();
#pragma unroll
    for (int mi = 0; mi < 2; mi++)
#pragma unroll
        for (int hh = 0; hh < 2; hh++) {
            float v = sqacc[mi][hh];
            v += __shfl_xor_sync(0xFFFFFFFF, v, 1);
            v += __shfl_xor_sync(0xFFFFFFFF, v, 2);
            if (tig == 0) atomicAdd(&sq[mw * 32 + mi * 16 + gid + hh * 8], v);
        }
    __syncthreads();
    if (tid < QT) sq[tid] = 1.0f / fmaxf(sqrtf(sq[tid]), NORM_EPS);
    for (int w = 0; w < 4; w++) {
        if (nw == w) {
#pragma unroll
            for (int mi = 0; mi < 2; mi++)
#pragma unroll
                for (int ni = 0; ni < 8; ni++) {
                    int r = mw * 32 + mi * 16 + gid;
                    int c = ni * 8 + tig * 2;
                    if (w == 0) {
                        Ured[r * 68 + c]           = U[mi][ni][0];
                        Ured[r * 68 + c + 1]       = U[mi][ni][1];
                        Ured[(r + 8) * 68 + c]     = U[mi][ni][2];
                        Ured[(r + 8) * 68 + c + 1] = U[mi][ni][3];
                    } else {
                        Ured[r * 68 + c]           += U[mi][ni][0];
                        Ured[r * 68 + c + 1]       += U[mi][ni][1];
                        Ured[(r + 8) * 68 + c]     += U[mi][ni][2];
                        Ured[(r + 8) * 68 + c + 1] += U[mi][ni][3];
                    }
                }
        }
        __syncthreads();
    }
#pragma unroll
    for (int i = 0; i < 4; i++) {
        int idx = tid + i * 512;
        int r = idx >> 4, c4 = (idx & 15) * 4;
        float sc = sq[r];
        float4 v = *(const float4*)(Ured + r * 68 + c4);
        uint2 hh;
        hh.x = packh2(v.x * sc, v.y * sc);
        hh.y = packh2(v.z * sc, v.w * sc);
        long gpos = ((long)(b * Sv + row0 + r)) * DM + h * 64 + c4;
        *(uint2*)&Aoh[gpos] = hh;
    }
}

// ===========================================================================
// small kernels
// ===========================================================================
// fp32 -> fp16 round (query)
__global__ void round_k(const float* __restrict__ x, h16* __restrict__ h, long n4)
{
    long i = (long)blockIdx.x * 256 + threadIdx.x;
    if (i >= n4) return;
    float4 v = *(const float4*)&x[i * 4];
    uint2 hh;
    hh.x = packh2(v.x, v.y);
    hh.y = packh2(v.z, v.w);
    *(uint2*)&h[i * 4] = hh;
}

// transpose + round-to-fp16 (weights, HvT)
__global__ void transpose_round_k(const float* __restrict__ in,
                                  h16* __restrict__ oh,
                                  long ldi, long ldo, int H,
                                  long sIb, long sIh, long sOz)
{
    __shared__ float t[32][33];
    int z = blockIdx.z, b = z / H, h = z - b * H;
    in += (long)b * sIb + (long)h * sIh;
    oh += (long)z * sOz;
    int x0 = blockIdx.x * 32, y0 = blockIdx.y * 32;
    int tx = threadIdx.x & 31, ty = threadIdx.x >> 5;
#pragma unroll
    for (int i = 0; i < 4; i++)
        t[ty + i * 8][tx] = in[(long)(y0 + ty + i * 8) * ldi + x0 + tx];
    __syncthreads();
#pragma unroll
    for (int i = 0; i < 4; i++)
        oh[(long)(x0 + ty + i * 8) * ldo + y0 + tx] = __float2half(t[tx][ty + i * 8]);
}

// LayerNorm -> fp16 (hi only)
__global__ void layernorm_round_k(const float* __restrict__ Z,
                                  h16* __restrict__ oh,
                                  const float* __restrict__ g, const float* __restrict__ be)
{
    __shared__ float red[256];
    int tid = threadIdx.x;
    const float* row = Z + (long)blockIdx.x * DL;
    float v[4];
#pragma unroll
    for (int t = 0; t < 4; t++) v[t] = row[tid + t * 256];
    float s = v[0] + v[1] + v[2] + v[3];
    red[tid] = s; __syncthreads();
    for (int off = 128; off > 0; off >>= 1) {
        if (tid < off) red[tid] += red[tid + off];
        __syncthreads();
    }
    float mu = red[0] * (1.0f / DL);
    __syncthreads();
    float vs = 0.f;
#pragma unroll
    for (int t = 0; t < 4; t++) { float d = v[t] - mu; vs += d * d; }
    red[tid] = vs; __syncthreads();
    for (int off = 128; off > 0; off >>= 1) {
        if (tid < off) red[tid] += red[tid + off];
        __syncthreads();
    }
    float rstd = rsqrtf(red[0] * (1.0f / DL) + LN_EPS);
    long base = (long)blockIdx.x * DL;
#pragma unroll
    for (int t = 0; t < 4; t++) {
        int i = tid + t * 256;
        oh[base + i] = __float2half((v[t] - mu) * rstd * g[i] + be[i]);
    }
}

// phasor for Q and R in one launch (hi-only outputs)
__global__ void phasor2_k(const float* __restrict__ QRH,
                          h16* __restrict__ Qch, h16* __restrict__ Rch,
                          const float* __restrict__ Wphi, const float* __restrict__ bphi)
{
    __shared__ float W[HD][HD];
    __shared__ float qrow[4][HD + 4];
    int tid = threadIdx.x;
    int j = tid & 63, g = tid >> 6;
    int which = blockIdx.y;
    for (int i = tid; i < HD * HD; i += 256) W[i >> 6][i & 63] = Wphi[i];
    __syncthreads();
    const float* base = QRH + (long)blockIdx.x * (3 * DM) + (which ? DM : 0);
    h16* oh = which ? Rch : Qch;
    long obase = (long)blockIdx.x * (NH * 2 * HD);
    float bj = bphi[j];
    for (int hb = 0; hb < NH; hb += 4) {
        int h = hb + g;
        qrow[g][j] = base[h * HD + j];
        __syncthreads();
        float phi = bj;
#pragma unroll 16
        for (int d = 0; d < HD; d++) phi += qrow[g][d] * W[d][j];
        float q = qrow[g][j];
        float sp, cp;
        sincosf(phi, &sp, &cp);
        long oc = obase + h * 2 * HD + j;
        oh[oc]      = __float2half(q * cp);
        oh[oc + HD] = __float2half(q * sp);
        __syncthreads();
    }
}

__global__ void concat3_k(const float* __restrict__ a, const float* __restrict__ b,
                          const float* __restrict__ c, float* __restrict__ o)
{
    int i = blockIdx.x * 256 + threadIdx.x;
    if (i < DM) o[i] = a[i];
    else if (i < 2 * DM) o[i] = b[i - DM];
    else if (i < 3 * DM) o[i] = c[i - 2 * DM];
}

// ===========================================================================
extern "C" void kernel_launch(void* const* d_in, const int* in_sizes, int n_in,
                              void* d_out, int out_size)
{
    const float* query = (const float*)d_in[0];
    const float* Wz   = (const float*)d_in[3];
    const float* bz   = (const float*)d_in[4];
    const float* ln_g = (const float*)d_in[5];
    const float* ln_b = (const float*)d_in[6];
    const float* Wq   = (const float*)d_in[7];
    const float* bq   = (const float*)d_in[8];
    const float* Wr   = (const float*)d_in[9];
    const float* br   = (const float*)d_in[10];
    const float* Wh   = (const float*)d_in[11];
    const float* bh   = (const float*)d_in[12];
    const float* Wphi = (const float*)d_in[13];
    const float* bphi = (const float*)d_in[14];
    const float* Wo   = (const float*)d_in[15];
    const float* bo   = (const float*)d_in[16];
    float* out = (float*)d_out;

    h16 *Qs_h, *WT_h, *Zs_h, *Qc_h, *Rc_h, *HvT_h, *Ao_h;
    float *Z, *QRH, *bqrh;
    cudaGetSymbolAddress((void**)&Qs_h, g_Qs_h);
    cudaGetSymbolAddress((void**)&WT_h, g_WT_h);
    cudaGetSymbolAddress((void**)&Z,    g_Z);
    cudaGetSymbolAddress((void**)&Zs_h, g_Zs_h);
    cudaGetSymbolAddress((void**)&QRH,  g_QRH);
    cudaGetSymbolAddress((void**)&bqrh, g_bqrh);
    cudaGetSymbolAddress((void**)&Qc_h, g_Qc_h);
    cudaGetSymbolAddress((void**)&Rc_h, g_Rc_h);
    cudaGetSymbolAddress((void**)&HvT_h, g_HvT_h);
    cudaGetSymbolAddress((void**)&Ao_h, g_Ao_h);

    const int SMG_kbuf = (128 + 128) * 72 * 2 * 2;  // 73,728 B
    const int SMG_stg  = 128 * (128 + 4) * 4;       // 67,584 B
    const int SMG = SMG_kbuf > SMG_stg ? SMG_kbuf : SMG_stg;
    cudaFuncSetAttribute(gemm_ps, cudaFuncAttributeMaxDynamicSharedMemorySize, SMG);
    cudaFuncSetAttribute(fused_attn_k, cudaFuncAttributeMaxDynamicSharedMemorySize, FA_SMEM);

    dim3 blk(256), gblk(512);
    long szW = (long)DM * DL;

    // 0) transpose+round weights; round query; combined bias
    transpose_round_k<<<dim3(32, 32, 1), blk>>>(Wz, WT_h + 0 * szW, DL, DM, 1, 0, 0, 0);
    transpose_round_k<<<dim3(32, 32, 1), blk>>>(Wq, WT_h + 1 * szW, DM, DL, 1, 0, 0, 0);
    transpose_round_k<<<dim3(32, 32, 1), blk>>>(Wr, WT_h + 2 * szW, DM, DL, 1, 0, 0, 0);
    transpose_round_k<<<dim3(32, 32, 1), blk>>>(Wh, WT_h + 3 * szW, DM, DL, 1, 0, 0, 0);
    transpose_round_k<<<dim3(32, 32, 1), blk>>>(Wo, WT_h + 4 * szW, DM, DM, 1, 0, 0, 0);
    round_k<<<(TOK * DM / 4 + 255) / 256, blk>>>(query, Qs_h, (long)TOK * DM / 4);
    concat3_k<<<12, blk>>>(bq, br, bh, bqrh);

    // 1) Z = query @ Wz + bz
    gemm_ps<<<dim3(DL / 128, TOK / 128, 1), gblk, SMG>>>(
        Qs_h, WT_h, bz, Z, DM, DM, DM, DL);

    // 2) LayerNorm -> fp16
    layernorm_round_k<<<TOK, blk>>>(Z, Zs_h, ln_g, ln_b);

    // 3) fused Q|R|H projection (N=3072)
    gemm_ps<<<dim3(3 * DM / 128, TOK / 128, 1), gblk, SMG>>>(
        Zs_h, WT_h + szW, bqrh, QRH, DL, DL, DL, 3 * DM);

    // 4) phasor -> Qc / Rc (one launch)
    phasor2_k<<<dim3(TOK, 2, 1), blk>>>(QRH, Qc_h, Rc_h, Wphi, bphi);

    // 5) Hv^T per (b,h), fp16-rounded (Hv = QRH cols [2048,3072))
    transpose_round_k<<<dim3(HD / 32, Sv / 32, Bv * NH), blk>>>(
        QRH + 2 * DM, HvT_h, 3 * DM, Sv, NH, (long)Sv * 3 * DM, HD, (long)HD * Sv);

    // 6) fused attention -> Ao fp16
    fused_attn_k<<<dim3(Sv / QT, 1, Bv * NH), gblk, FA_SMEM>>>(
        Qc_h, Rc_h, HvT_h, Ao_h);

    // 7) out = Ao @ Wo + bo
    gemm_ps<<<dim3(DM / 128, TOK / 128, 1), gblk, SMG>>>(
        Ao_h, WT_h + 4 * szW, bo, out, DM, DM, DM, DM);
}